// round 9
// baseline (speedup 1.0000x reference)
#include <cuda_runtime.h>
#include <cstdint>
#include <cmath>
#include <cstring>
#include <complex>
#include <cstdlib>

#define NT 256
struct TPParams {
    float cg[384]; float coeff[3];
    int cgo[12], woff[12], wpo[12], m3s[12];
};

__device__ uint32_t g_wp[2244608];   // W as half2 k-pairs (prepass output)

// smem: [0:1536) cg, [1536:51456) sx2 192*65*4, [51456:107776) arena
#define OX2 1536
#define OAR 51456
#define SMT 107776

__device__ __forceinline__ uint32_t pack2(float lo, float hi){
    uint32_t r; asm("cvt.rn.f16x2.f32 %0,%1,%2;":"=r"(r):"f"(hi),"f"(lo)); return r;
}
__device__ __forceinline__ void mma16(float* d,const uint32_t* a,const uint32_t* b){
    asm volatile("mma.sync.aligned.m16n8k16.row.col.f32.f16.f16.f32 "
        "{%0,%1,%2,%3},{%4,%5,%6,%7},{%8,%9},{%0,%1,%2,%3};"
        :"+f"(d[0]),"+f"(d[1]),"+f"(d[2]),"+f"(d[3])
        :"r"(a[0]),"r"(a[1]),"r"(a[2]),"r"(a[3]),"r"(b[0]),"r"(b[1]));
}

// ---------------- W prepass: fp32 -> half2 k-pair layout ---------------------
__global__ void wpre_kernel(const float* __restrict__ w,
                            const __grid_constant__ TPParams P){
    int r = blockIdx.x*256 + threadIdx.x;
    if(r >= P.wpo[11]) return;
    int t = 0;
    while(r >= P.wpo[t+1]) ++t;
    int loc = r - P.wpo[t], M3 = P.m3s[t];
    int pr = loc / M3, w_ = loc - pr*M3;
    const float* s = w + P.woff[t] + (size_t)2*pr*M3 + w_;
    g_wp[r] = pack2(s[0], s[M3]);
}

// ---------------- fused path: stage + P-compute + mma pipeline ---------------
template<int M3,int L3,int L1,int L2,int M1,int M2,int RG>
__device__ __forceinline__ void do_path(
    const float* __restrict__ gx1, const float* __restrict__ gx2,
    int wpo, const float* __restrict__ cg,
    float* sx2, char* arena,
    float (&acc)[L3][M3*RG/64][4/RG][4])
{
    constexpr int CGn=8/RG, CPW=M3/CGn, NC=CPW/8, R2=4/RG, WS=M3+8;
    constexpr int WB=16*WS*4, AB=L3*1280*4, NCH=M1*M2/32;
    uint32_t* sWb[2]={(uint32_t*)arena,(uint32_t*)(arena+WB)};
    uint32_t* sAb[2]={(uint32_t*)(arena+2*WB),(uint32_t*)(arena+2*WB+AB)};
    const int tid=threadIdx.x, wid=tid>>5, lane=tid&31;
    const int cgp=wid/RG, rowg=wid%RG, gID=lane>>2, tIG=lane&3;
    const int q=tid&15, bg=tid>>4;

    __syncthreads();                 // prior phase fully drained
    constexpr int C2q=(M2*L2)/4;
    for(int idx=tid; idx<64*C2q; idx+=NT){
        int b=idx/C2q, qq=idx-b*C2q;
        float4 v=*(const float4*)(gx2+b*480+4*qq);
        float vv[4]={v.x,v.y,v.z,v.w};
#pragma unroll
        for(int e=0;e<4;++e) sx2[(4*qq+e)*65+b]=vv[e];
    }
    __syncthreads();

    float rx1[4][L1];
    auto loadx1=[&](int u){
#pragma unroll
        for(int it=0;it<4;++it)
#pragma unroll
            for(int i=0;i<L1;++i)
                rx1[it][i]=gx1[(it*16+bg)*480+u*L1+i];
    };
    auto stageW=[&](int n){
        uint32_t* d=sWb[n&1];
        const uint4* g4=(const uint4*)(g_wp + wpo + (size_t)n*16*M3);
        constexpr int TOT=16*M3/4;
#pragma unroll
        for(int t2=0;t2<(TOT+NT-1)/NT;++t2){
            int idx=t2*NT+tid;
            if(TOT%NT==0 || idx<TOT){
                int p=idx/(M3/4), wq=idx-p*(M3/4);
                *(uint4*)(d+p*WS+4*wq)=g4[idx];
            }
        }
    };
    auto compP=[&](int n){
        uint32_t* d=sAb[n&1];
        const int v0=(n*32)&(M2-1);
        const float* c2a=sx2+(v0+2*q)*L2*65;
        const float* c2b=c2a+L2*65;
#pragma unroll
        for(int it=0;it<4;++it){
            const int b=it*16+bg;
            float pa[L3], pb[L3];
#pragma unroll
            for(int k=0;k<L3;++k){ pa[k]=0.f; pb[k]=0.f; }
#pragma unroll
            for(int i=0;i<L1;++i){
                const float xi=rx1[it][i];
#pragma unroll
                for(int j=0;j<L2;++j){
                    float xa=xi*c2a[j*65+b], xb=xi*c2b[j*65+b];
#pragma unroll
                    for(int k=0;k<L3;++k){
                        float c=cg[(i*L2+j)*L3+k];
                        pa[k]+=c*xa; pb[k]+=c*xb;
                    }
                }
            }
#pragma unroll
            for(int k=0;k<L3;++k) d[k*1280+b*20+q]=pack2(pa[k],pb[k]);
        }
    };

    loadx1(0); stageW(0); compP(0);
#pragma unroll 1
    for(int n=0;n<NCH;++n){
        __syncthreads();             // bufs(n) ready; MMA(n-1) done
        {   // MMA(n)
            const uint32_t* sWc=sWb[n&1];
            const uint32_t* sAc=sAb[n&1];
#pragma unroll
            for(int ks=0;ks<2;++ks){
                uint32_t a[L3][R2][4];
#pragma unroll
                for(int k=0;k<L3;++k)
#pragma unroll
                    for(int r2=0;r2<R2;++r2){
                        const uint32_t* Ab=sAc+k*1280
                            +(rowg*(64/RG)+r2*16+gID)*20+ks*8+tIG;
                        a[k][r2][0]=Ab[0];   a[k][r2][1]=Ab[160];
                        a[k][r2][2]=Ab[4];   a[k][r2][3]=Ab[164];
                    }
                uint32_t bb[NC][2];
#pragma unroll
                for(int nc=0;nc<NC;++nc){
                    const uint32_t* Bb=sWc+(ks*8+tIG)*WS+cgp*CPW+nc*8+gID;
                    bb[nc][0]=Bb[0]; bb[nc][1]=Bb[4*WS];
                }
#pragma unroll
                for(int k=0;k<L3;++k)
#pragma unroll
                    for(int nc=0;nc<NC;++nc)
#pragma unroll
                        for(int r2=0;r2<R2;++r2)
                            mma16(acc[k][nc][r2],a[k][r2],bb[nc]);
            }
        }
        if(n+1<NCH){                 // stage next chunk (other buffers)
            if((((n+1)*32)&(M2-1))==0) loadx1((n+1)*32/M2);
            stageW(n+1); compP(n+1);
        }
    }
}

template<int M3,int L3,int OFF3,int RG>
__device__ __forceinline__ void epilogue(float (&acc)[L3][M3*RG/64][4/RG][4],
    float* __restrict__ out,int tile,float coeff)
{
    constexpr int CGn=8/RG, CPW=M3/CGn, NC=CPW/8, R2=4/RG;
    const int tid=threadIdx.x, wid=tid>>5, lane=tid&31;
    const int cgp=wid/RG, rowg=wid%RG, gID=lane>>2, tIG=lane&3;
#pragma unroll
    for(int k=0;k<L3;++k)
#pragma unroll
        for(int nc=0;nc<NC;++nc)
#pragma unroll
            for(int r2=0;r2<R2;++r2){
                const int wc=cgp*CPW+nc*8+2*tIG;
                const int row=tile*64+rowg*(64/RG)+r2*16+gID;
                float* po=out+(size_t)row*480+OFF3;
                po[(wc+0)*L3+k]=coeff*acc[k][nc][r2][0];
                po[(wc+1)*L3+k]=coeff*acc[k][nc][r2][1];
                po+=8*480;
                po[(wc+0)*L3+k]=coeff*acc[k][nc][r2][2];
                po[(wc+1)*L3+k]=coeff*acc[k][nc][r2][3];
            }
}

__global__ void __launch_bounds__(NT,2)
tp_kernel(const float* __restrict__ x1,const float* __restrict__ x2,
          float* __restrict__ out,const __grid_constant__ TPParams P)
{
    extern __shared__ char sm[];
    float* scg=(float*)sm;
    for(int e=threadIdx.x;e<384;e+=NT) scg[e]=P.cg[e];
    const int tile=blockIdx.y;
    const float* X1=x1+(size_t)tile*64*480;
    const float* X2=x2+(size_t)tile*64*480;
    float* sx2=(float*)(sm+OX2);
    char* ar=sm+OAR;

    if(blockIdx.x==0){
        float acc[1][4][2][4]={};
        do_path<128,1,1,1,128,128,2>(X1,    X2,    P.wpo[0],scg+P.cgo[0],sx2,ar,acc);
        do_path<128,1,3,3, 64, 64,2>(X1+128,X2+128,P.wpo[4],scg+P.cgo[4],sx2,ar,acc);
        do_path<128,1,5,5, 32, 32,2>(X1+320,X2+320,P.wpo[9],scg+P.cgo[9],sx2,ar,acc);
        epilogue<128,1,0,2>(acc,out,tile,P.coeff[0]);
    } else if(blockIdx.x==1){
        float acc[3][4][1][4]={};
        do_path<64,3,1,3,128, 64,4>(X1,    X2+128,P.wpo[1],scg+P.cgo[1],sx2,ar,acc);
        do_path<64,3,3,1, 64,128,4>(X1+128,X2,    P.wpo[3],scg+P.cgo[3],sx2,ar,acc);
        do_path<64,3,3,5, 64, 32,4>(X1+128,X2+320,P.wpo[6],scg+P.cgo[6],sx2,ar,acc);
        do_path<64,3,5,3, 32, 64,4>(X1+320,X2+128,P.wpo[8],scg+P.cgo[8],sx2,ar,acc);
        epilogue<64,3,128,4>(acc,out,tile,P.coeff[1]);
    } else {
        float acc[5][2][1][4]={};
        do_path<32,5,1,5,128, 32,4>(X1,    X2+320,P.wpo[2], scg+P.cgo[2], sx2,ar,acc);
        do_path<32,5,3,3, 64, 64,4>(X1+128,X2+128,P.wpo[5], scg+P.cgo[5], sx2,ar,acc);
        do_path<32,5,5,1, 32,128,4>(X1+320,X2,    P.wpo[7], scg+P.cgo[7], sx2,ar,acc);
        do_path<32,5,5,5, 32, 32,4>(X1+320,X2+320,P.wpo[10],scg+P.cgo[10],sx2,ar,acc);
        epilogue<32,5,320,4>(acc,out,tile,P.coeff[2]);
    }
}

// ---------------------- host: CG construction (verified) --------------------

typedef std::complex<double> cpx;
static double fct(int n){double r=1.0;for(int i=2;i<=n;++i)r*=i;return r;}

static void change_basis(int l, cpx q[5][5]){
    for(int a=0;a<5;++a)for(int b=0;b<5;++b)q[a][b]=cpx(0,0);
    const double s2=1.0/std::sqrt(2.0);
    for(int m=-l;m<0;++m){ q[l+m][l-m]=cpx(s2,0); q[l+m][l+m]=cpx(0,-s2); }
    q[l][l]=cpx(1,0);
    for(int m=1;m<=l;++m){
        double sg=(m&1)?-1.0:1.0;
        q[l+m][l+m]=cpx(sg*s2,0); q[l+m][l-m]=cpx(0,sg*s2);
    }
    cpx ph(1,0);
    for(int t=0;t<l;++t)ph*=cpx(0,-1);
    for(int a=0;a<2*l+1;++a)for(int b=0;b<2*l+1;++b)q[a][b]*=ph;
}

static void real_cg(int l1,int l2,int l3,float outc[5][5][5]){
    cpx Q1[5][5],Q2[5][5],Q3[5][5];
    change_basis(l1,Q1); change_basis(l2,Q2); change_basis(l3,Q3);
    double C[5][5][5]; memset(C,0,sizeof(C));
    for(int m1=-l1;m1<=l1;++m1)
        for(int m2=-l2;m2<=l2;++m2){
            int m3=m1+m2;
            if(m3<-l3||m3>l3)continue;
            double pref=std::sqrt((2.0*l3+1.0)
                *fct(l3+l1-l2)*fct(l3-l1+l2)*fct(l1+l2-l3)/fct(l1+l2+l3+1)
                *fct(l3+m3)*fct(l3-m3)*fct(l1-m1)*fct(l1+m1)*fct(l2-m2)*fct(l2+m2));
            double s=0.0;
            for(int k=0;k<=l1+l2-l3;++k){
                if(l1-m1-k<0||l2+m2-k<0||l3-l2+m1+k<0||l3-l1-m2+k<0)continue;
                double d=fct(k)*fct(l1+l2-l3-k)*fct(l1-m1-k)
                        *fct(l2+m2-k)*fct(l3-l2+m1+k)*fct(l3-l1-m2+k);
                s+=((k&1)?-1.0:1.0)/d;
            }
            C[l1+m1][l2+m2][l3+m3]=pref*s;
        }
    int n1=2*l1+1,n2=2*l2+1,n3=2*l3+1;
    double Rr[5][5][5],nrm=0.0;
    for(int j=0;j<n1;++j)
        for(int lb=0;lb<n2;++lb)
            for(int nn=0;nn<n3;++nn){
                cpx a(0,0);
                for(int i=0;i<n1;++i)
                    for(int kk=0;kk<n2;++kk)
                        for(int m=0;m<n3;++m)
                            if(C[i][kk][m]!=0.0)
                                a+=Q1[i][j]*Q2[kk][lb]*Q3[m][nn]*C[i][kk][m];
                Rr[j][lb][nn]=a.real();
                nrm+=a.real()*a.real();
            }
    nrm=std::sqrt(nrm);
    for(int j=0;j<5;++j)for(int lb=0;lb<5;++lb)for(int nn=0;nn<5;++nn)
        outc[j][lb][nn]=(j<n1&&lb<n2&&nn<n3)?(float)(Rr[j][lb][nn]/nrm):0.f;
}

static void build_params(TPParams& P){
    memset(&P,0,sizeof(P));
    const int M_[3]={128,64,32}, L_[3]={0,1,2}, Pa[3]={1,-1,1};
    long long fan[3]={0,0,0};
    int woff=0, cgo=0, idx=0;
    for(int i1=0;i1<3;++i1)for(int i2=0;i2<3;++i2)for(int i3=0;i3<3;++i3){
        int l1=L_[i1],l2=L_[i2],l3=L_[i3];
        if(Pa[i1]*Pa[i2]!=Pa[i3])continue;
        if(l3<abs(l1-l2)||l3>l1+l2)continue;
        float C[5][5][5];
        real_cg(l1,l2,l3,C);
        P.woff[idx]=woff; P.cgo[idx]=cgo;
        P.wpo[idx]=woff/2; P.m3s[idx]=M_[i3];
        int n1=2*l1+1,n2=2*l2+1,n3=2*l3+1;
        for(int i=0;i<n1;++i)for(int j=0;j<n2;++j)for(int k=0;k<n3;++k)
            P.cg[cgo++]=C[i][j][k];
        woff+=M_[i1]*M_[i2]*M_[i3];
        fan[i3]+=(long long)M_[i1]*M_[i2];
        ++idx;
    }
    P.wpo[11]=woff/2;
    for(int t=0;t<3;++t)
        P.coeff[t]=(float)std::sqrt((double)(2*L_[t]+1)/(double)fan[t]);
}

// ------------------------------ entry ---------------------------------------

extern "C" void kernel_launch(void* const* d_in, const int* in_sizes, int n_in,
                              void* d_out, int out_size) {
    TPParams P;
    build_params(P);
    wpre_kernel<<<(P.wpo[11]+255)/256, 256>>>((const float*)d_in[2], P);
    cudaFuncSetAttribute(tp_kernel, cudaFuncAttributeMaxDynamicSharedMemorySize, SMT);
    tp_kernel<<<dim3(3,128), NT, SMT>>>(
        (const float*)d_in[0], (const float*)d_in[1], (float*)d_out, P);
}

// round 10
// speedup vs baseline: 1.0946x; 1.0946x over previous
#include <cuda_runtime.h>
#include <cuda_fp16.h>
#include <cstdint>
#include <cmath>
#include <cstring>
#include <complex>
#include <cstdlib>

#define NT 256
struct TPParams {
    float cg[384]; float coeff[3];
    int cgo[12], woff[12], wpo[12], m3s[12];
};

__device__ uint32_t g_wp[2244608];   // W as half2 k-pairs (prepass output)

// smem: [0:1536) cg, [1536:26880) sx2h (half2, stride 66), [26880) sA x2 bufs
#define OX2 1536
#define OSA 26880
#define SMT 78080

__device__ __forceinline__ uint32_t pack2(float lo, float hi){
    uint32_t r; asm("cvt.rn.f16x2.f32 %0,%1,%2;":"=r"(r):"f"(hi),"f"(lo)); return r;
}
__device__ __forceinline__ uint32_t smem_u32(const void* p){
    uint32_t a;
    asm("{ .reg .u64 t; cvta.to.shared.u64 t, %1; cvt.u32.u64 %0, t; }":"=r"(a):"l"(p));
    return a;
}
__device__ __forceinline__ void mma16(float* d,const uint32_t* a,const uint32_t* b){
    asm volatile("mma.sync.aligned.m16n8k16.row.col.f32.f16.f16.f32 "
        "{%0,%1,%2,%3},{%4,%5,%6,%7},{%8,%9},{%0,%1,%2,%3};"
        :"+f"(d[0]),"+f"(d[1]),"+f"(d[2]),"+f"(d[3])
        :"r"(a[0]),"r"(a[1]),"r"(a[2]),"r"(a[3]),"r"(b[0]),"r"(b[1]));
}
#define LDSM4(r,addr) asm volatile( \
    "ldmatrix.sync.aligned.m8n8.x4.shared.b16 {%0,%1,%2,%3},[%4];" \
    :"=r"((r)[0]),"=r"((r)[1]),"=r"((r)[2]),"=r"((r)[3]):"r"(addr))

// ---------------- W prepass: fp32 -> half2 k-pair layout ---------------------
__global__ void wpre_kernel(const float* __restrict__ w,
                            const __grid_constant__ TPParams P){
    int r = blockIdx.x*256 + threadIdx.x;
    if(r >= P.wpo[11]) return;
    int t = 0;
    while(r >= P.wpo[t+1]) ++t;
    int loc = r - P.wpo[t], M3 = P.m3s[t];
    int pr = loc / M3, w_ = loc - pr*M3;
    const float* s = w + P.woff[t] + (size_t)2*pr*M3 + w_;
    g_wp[r] = pack2(s[0], s[M3]);
}

// ---------------- fused path ------------------------------------------------
template<int M3,int L3,int L1,int L2,int M1,int M2,int RG>
__device__ __forceinline__ void do_path(
    const float* __restrict__ gx1, const float* __restrict__ gx2,
    int wpo, const float* __restrict__ cg,
    uint32_t* sx2h, uint32_t* sA0, uint32_t* sA1, uint32_t sA0a, uint32_t sA1a,
    float (&acc)[L3][M3*RG/64][4/RG][4])
{
    constexpr int CGn=8/RG, CPW=M3/CGn, NC=CPW/8, R2=4/RG;
    constexpr int NCH=M1*M2/32, C=(M2/2)*L2;
    const int tid=threadIdx.x, wid=tid>>5, lane=tid&31;
    const int cgp=wid/RG, rowg=wid%RG, gID=lane>>2, tIG=lane&3;
    const int q=tid&15, bg=tid>>4;
    const int rbase=rowg*(64/RG)+(lane&7)+((lane>>3)&1)*8;
    const int qb=((lane>>4)&1)*16;

    __syncthreads();                 // prior path's MMA fully drained
    for(int idx=tid; idx<64*C; idx+=NT){
        int b=idx/C, c=idx-b*C, vp=c/L2, j=c-vp*L2;
        float lo=gx2[b*480+(2*vp)*L2+j], hi=gx2[b*480+(2*vp+1)*L2+j];
        sx2h[c*66+b]=pack2(lo,hi);
    }
    __syncthreads();

    float rx1[4][L1];
    auto loadx1=[&](int u){
#pragma unroll
        for(int it=0;it<4;++it)
#pragma unroll
            for(int i=0;i<L1;++i)
                rx1[it][i]=gx1[(it*16+bg)*480+u*L1+i];
    };
    auto compP=[&](int n){
        uint32_t* d=(n&1)?sA1:sA0;
        const int vp0=((n*32)&(M2-1))>>1;
        const uint32_t* c2=sx2h+(vp0+q)*L2*66;
#pragma unroll
        for(int it=0;it<4;++it){
            const int b=it*16+bg;
            float pa[L3], pb[L3];
#pragma unroll
            for(int k=0;k<L3;++k){ pa[k]=0.f; pb[k]=0.f; }
#pragma unroll
            for(int i=0;i<L1;++i){
                const float xi=rx1[it][i];
#pragma unroll
                for(int j=0;j<L2;++j){
                    uint32_t cw=c2[j*66+b];
                    float2 cf=__half22float2(*(__half2*)&cw);
                    float xa=xi*cf.x, xb=xi*cf.y;
#pragma unroll
                    for(int k=0;k<L3;++k){
                        float cc=cg[(i*L2+j)*L3+k];
                        pa[k]+=cc*xa; pb[k]+=cc*xb;
                    }
                }
            }
#pragma unroll
            for(int k=0;k<L3;++k) d[k*1280+b*20+q]=pack2(pa[k],pb[k]);
        }
    };

    loadx1(0); compP(0);
#pragma unroll 1
    for(int n=0;n<NCH;++n){
        // B fragments direct from global (sync-independent, early issue)
        uint32_t breg[2][NC][2];
#pragma unroll
        for(int ks=0;ks<2;++ks)
#pragma unroll
            for(int nc=0;nc<NC;++nc){
                const uint32_t* gB=g_wp+wpo+(size_t)(16*n+ks*8+tIG)*M3
                                   +cgp*CPW+nc*8+gID;
                breg[ks][nc][0]=gB[0]; breg[ks][nc][1]=gB[4*M3];
            }
        __syncthreads();             // sA(n) ready; prev MMA done
        const uint32_t sAa=(n&1)?sA1a:sA0a;
#pragma unroll
        for(int ks=0;ks<2;++ks){
            uint32_t a[L3][R2][4];
#pragma unroll
            for(int k=0;k<L3;++k)
#pragma unroll
                for(int r2=0;r2<R2;++r2)
                    LDSM4(a[k][r2], sAa+(k*1280+(rbase+r2*16)*20)*4+qb+ks*32);
#pragma unroll
            for(int k=0;k<L3;++k)
#pragma unroll
                for(int nc=0;nc<NC;++nc)
#pragma unroll
                    for(int r2=0;r2<R2;++r2)
                        mma16(acc[k][nc][r2],a[k][r2],breg[ks][nc]);
        }
        if(n+1<NCH){
            if((((n+1)*32)&(M2-1))==0) loadx1((n+1)*32/M2);
            compP(n+1);
        }
    }
}

template<int M3,int L3,int OFF3,int RG>
__device__ __forceinline__ void epilogue(float (&acc)[L3][M3*RG/64][4/RG][4],
    float* __restrict__ out,int tile,float coeff)
{
    constexpr int CGn=8/RG, CPW=M3/CGn, NC=CPW/8, R2=4/RG;
    const int tid=threadIdx.x, wid=tid>>5, lane=tid&31;
    const int cgp=wid/RG, rowg=wid%RG, gID=lane>>2, tIG=lane&3;
#pragma unroll
    for(int k=0;k<L3;++k)
#pragma unroll
        for(int nc=0;nc<NC;++nc)
#pragma unroll
            for(int r2=0;r2<R2;++r2){
                const int wc=cgp*CPW+nc*8+2*tIG;
                const int row=tile*64+rowg*(64/RG)+r2*16+gID;
                float* po=out+(size_t)row*480+OFF3;
                po[(wc+0)*L3+k]=coeff*acc[k][nc][r2][0];
                po[(wc+1)*L3+k]=coeff*acc[k][nc][r2][1];
                po+=8*480;
                po[(wc+0)*L3+k]=coeff*acc[k][nc][r2][2];
                po[(wc+1)*L3+k]=coeff*acc[k][nc][r2][3];
            }
}

__global__ void __launch_bounds__(NT,2)
tp_kernel(const float* __restrict__ x1,const float* __restrict__ x2,
          float* __restrict__ out,const __grid_constant__ TPParams P)
{
    extern __shared__ char sm[];
    float* scg=(float*)sm;
    for(int e=threadIdx.x;e<384;e+=NT) scg[e]=P.cg[e];
    const int tile=blockIdx.y;
    const float* X1=x1+(size_t)tile*64*480;
    const float* X2=x2+(size_t)tile*64*480;
    uint32_t* sx2h=(uint32_t*)(sm+OX2);

    if(blockIdx.x==0){
        uint32_t* A0=(uint32_t*)(sm+OSA); uint32_t* A1=(uint32_t*)(sm+OSA+5120);
        uint32_t a0=smem_u32(A0), a1=smem_u32(A1);
        float acc[1][4][2][4]={};
        do_path<128,1,1,1,128,128,2>(X1,    X2,    P.wpo[0],scg+P.cgo[0],sx2h,A0,A1,a0,a1,acc);
        do_path<128,1,3,3, 64, 64,2>(X1+128,X2+128,P.wpo[4],scg+P.cgo[4],sx2h,A0,A1,a0,a1,acc);
        do_path<128,1,5,5, 32, 32,2>(X1+320,X2+320,P.wpo[9],scg+P.cgo[9],sx2h,A0,A1,a0,a1,acc);
        epilogue<128,1,0,2>(acc,out,tile,P.coeff[0]);
    } else if(blockIdx.x==1){
        uint32_t* A0=(uint32_t*)(sm+OSA); uint32_t* A1=(uint32_t*)(sm+OSA+15360);
        uint32_t a0=smem_u32(A0), a1=smem_u32(A1);
        float acc[3][4][1][4]={};
        do_path<64,3,1,3,128, 64,4>(X1,    X2+128,P.wpo[1],scg+P.cgo[1],sx2h,A0,A1,a0,a1,acc);
        do_path<64,3,3,1, 64,128,4>(X1+128,X2,    P.wpo[3],scg+P.cgo[3],sx2h,A0,A1,a0,a1,acc);
        do_path<64,3,3,5, 64, 32,4>(X1+128,X2+320,P.wpo[6],scg+P.cgo[6],sx2h,A0,A1,a0,a1,acc);
        do_path<64,3,5,3, 32, 64,4>(X1+320,X2+128,P.wpo[8],scg+P.cgo[8],sx2h,A0,A1,a0,a1,acc);
        epilogue<64,3,128,4>(acc,out,tile,P.coeff[1]);
    } else {
        uint32_t* A0=(uint32_t*)(sm+OSA); uint32_t* A1=(uint32_t*)(sm+OSA+25600);
        uint32_t a0=smem_u32(A0), a1=smem_u32(A1);
        float acc[5][2][1][4]={};
        do_path<32,5,1,5,128, 32,4>(X1,    X2+320,P.wpo[2], scg+P.cgo[2], sx2h,A0,A1,a0,a1,acc);
        do_path<32,5,3,3, 64, 64,4>(X1+128,X2+128,P.wpo[5], scg+P.cgo[5], sx2h,A0,A1,a0,a1,acc);
        do_path<32,5,5,1, 32,128,4>(X1+320,X2,    P.wpo[7], scg+P.cgo[7], sx2h,A0,A1,a0,a1,acc);
        do_path<32,5,5,5, 32, 32,4>(X1+320,X2+320,P.wpo[10],scg+P.cgo[10],sx2h,A0,A1,a0,a1,acc);
        epilogue<32,5,320,4>(acc,out,tile,P.coeff[2]);
    }
}

// ---------------------- host: CG construction (verified) --------------------

typedef std::complex<double> cpx;
static double fct(int n){double r=1.0;for(int i=2;i<=n;++i)r*=i;return r;}

static void change_basis(int l, cpx q[5][5]){
    for(int a=0;a<5;++a)for(int b=0;b<5;++b)q[a][b]=cpx(0,0);
    const double s2=1.0/std::sqrt(2.0);
    for(int m=-l;m<0;++m){ q[l+m][l-m]=cpx(s2,0); q[l+m][l+m]=cpx(0,-s2); }
    q[l][l]=cpx(1,0);
    for(int m=1;m<=l;++m){
        double sg=(m&1)?-1.0:1.0;
        q[l+m][l+m]=cpx(sg*s2,0); q[l+m][l-m]=cpx(0,sg*s2);
    }
    cpx ph(1,0);
    for(int t=0;t<l;++t)ph*=cpx(0,-1);
    for(int a=0;a<2*l+1;++a)for(int b=0;b<2*l+1;++b)q[a][b]*=ph;
}

static void real_cg(int l1,int l2,int l3,float outc[5][5][5]){
    cpx Q1[5][5],Q2[5][5],Q3[5][5];
    change_basis(l1,Q1); change_basis(l2,Q2); change_basis(l3,Q3);
    double C[5][5][5]; memset(C,0,sizeof(C));
    for(int m1=-l1;m1<=l1;++m1)
        for(int m2=-l2;m2<=l2;++m2){
            int m3=m1+m2;
            if(m3<-l3||m3>l3)continue;
            double pref=std::sqrt((2.0*l3+1.0)
                *fct(l3+l1-l2)*fct(l3-l1+l2)*fct(l1+l2-l3)/fct(l1+l2+l3+1)
                *fct(l3+m3)*fct(l3-m3)*fct(l1-m1)*fct(l1+m1)*fct(l2-m2)*fct(l2+m2));
            double s=0.0;
            for(int k=0;k<=l1+l2-l3;++k){
                if(l1-m1-k<0||l2+m2-k<0||l3-l2+m1+k<0||l3-l1-m2+k<0)continue;
                double d=fct(k)*fct(l1+l2-l3-k)*fct(l1-m1-k)
                        *fct(l2+m2-k)*fct(l3-l2+m1+k)*fct(l3-l1-m2+k);
                s+=((k&1)?-1.0:1.0)/d;
            }
            C[l1+m1][l2+m2][l3+m3]=pref*s;
        }
    int n1=2*l1+1,n2=2*l2+1,n3=2*l3+1;
    double Rr[5][5][5],nrm=0.0;
    for(int j=0;j<n1;++j)
        for(int lb=0;lb<n2;++lb)
            for(int nn=0;nn<n3;++nn){
                cpx a(0,0);
                for(int i=0;i<n1;++i)
                    for(int kk=0;kk<n2;++kk)
                        for(int m=0;m<n3;++m)
                            if(C[i][kk][m]!=0.0)
                                a+=Q1[i][j]*Q2[kk][lb]*Q3[m][nn]*C[i][kk][m];
                Rr[j][lb][nn]=a.real();
                nrm+=a.real()*a.real();
            }
    nrm=std::sqrt(nrm);
    for(int j=0;j<5;++j)for(int lb=0;lb<5;++lb)for(int nn=0;nn<5;++nn)
        outc[j][lb][nn]=(j<n1&&lb<n2&&nn<n3)?(float)(Rr[j][lb][nn]/nrm):0.f;
}

static void build_params(TPParams& P){
    memset(&P,0,sizeof(P));
    const int M_[3]={128,64,32}, L_[3]={0,1,2}, Pa[3]={1,-1,1};
    long long fan[3]={0,0,0};
    int woff=0, cgo=0, idx=0;
    for(int i1=0;i1<3;++i1)for(int i2=0;i2<3;++i2)for(int i3=0;i3<3;++i3){
        int l1=L_[i1],l2=L_[i2],l3=L_[i3];
        if(Pa[i1]*Pa[i2]!=Pa[i3])continue;
        if(l3<abs(l1-l2)||l3>l1+l2)continue;
        float C[5][5][5];
        real_cg(l1,l2,l3,C);
        P.woff[idx]=woff; P.cgo[idx]=cgo;
        P.wpo[idx]=woff/2; P.m3s[idx]=M_[i3];
        int n1=2*l1+1,n2=2*l2+1,n3=2*l3+1;
        for(int i=0;i<n1;++i)for(int j=0;j<n2;++j)for(int k=0;k<n3;++k)
            P.cg[cgo++]=C[i][j][k];
        woff+=M_[i1]*M_[i2]*M_[i3];
        fan[i3]+=(long long)M_[i1]*M_[i2];
        ++idx;
    }
    P.wpo[11]=woff/2;
    for(int t=0;t<3;++t)
        P.coeff[t]=(float)std::sqrt((double)(2*L_[t]+1)/(double)fan[t]);
}

// ------------------------------ entry ---------------------------------------

extern "C" void kernel_launch(void* const* d_in, const int* in_sizes, int n_in,
                              void* d_out, int out_size) {
    TPParams P;
    build_params(P);
    wpre_kernel<<<(P.wpo[11]+255)/256, 256>>>((const float*)d_in[2], P);
    cudaFuncSetAttribute(tp_kernel, cudaFuncAttributeMaxDynamicSharedMemorySize, SMT);
    tp_kernel<<<dim3(3,128), NT, SMT>>>(
        (const float*)d_in[0], (const float*)d_in[1], (float*)d_out, P);
}

// round 11
// speedup vs baseline: 1.2174x; 1.1121x over previous
#include <cuda_runtime.h>
#include <cuda_fp16.h>
#include <cstdint>
#include <cmath>
#include <cstring>
#include <complex>
#include <cstdlib>

#define NT 256
struct TPParams {
    float cg[384]; float coeff[3];
    int cgo[12], woff[12], wpo[12], m3s[12];
};

__device__ uint32_t g_wp[2244608];   // W as half2 k-pairs (prepass output)

// smem: cg[0:1536) | sx2h[1536:26880) | sA x2 | sW x2 (per-variant offsets)
#define OX2 1536
#define OSA 26880
#define SMT 83200

__device__ __forceinline__ uint32_t pack2(float lo, float hi){
    uint32_t r; asm("cvt.rn.f16x2.f32 %0,%1,%2;":"=r"(r):"f"(hi),"f"(lo)); return r;
}
__device__ __forceinline__ uint32_t smem_u32(const void* p){
    uint32_t a;
    asm("{ .reg .u64 t; cvta.to.shared.u64 t, %1; cvt.u32.u64 %0, t; }":"=r"(a):"l"(p));
    return a;
}
__device__ __forceinline__ void mma16(float* d,const uint32_t* a,const uint32_t* b){
    asm volatile("mma.sync.aligned.m16n8k16.row.col.f32.f16.f16.f32 "
        "{%0,%1,%2,%3},{%4,%5,%6,%7},{%8,%9},{%0,%1,%2,%3};"
        :"+f"(d[0]),"+f"(d[1]),"+f"(d[2]),"+f"(d[3])
        :"r"(a[0]),"r"(a[1]),"r"(a[2]),"r"(a[3]),"r"(b[0]),"r"(b[1]));
}
#define LDSM4(r,addr) asm volatile( \
    "ldmatrix.sync.aligned.m8n8.x4.shared.b16 {%0,%1,%2,%3},[%4];" \
    :"=r"((r)[0]),"=r"((r)[1]),"=r"((r)[2]),"=r"((r)[3]):"r"(addr))

// ---------------- W prepass: fp32 -> half2 k-pair layout ---------------------
__global__ void wpre_kernel(const float* __restrict__ w,
                            const __grid_constant__ TPParams P){
    int r = blockIdx.x*256 + threadIdx.x;
    if(r >= P.wpo[11]) return;
    int t = 0;
    while(r >= P.wpo[t+1]) ++t;
    int loc = r - P.wpo[t], M3 = P.m3s[t];
    int pr = loc / M3, w_ = loc - pr*M3;
    const float* s = w + P.woff[t] + (size_t)2*pr*M3 + w_;
    g_wp[r] = pack2(s[0], s[M3]);
}

// ---------------- fused path ------------------------------------------------
template<int M3,int L3,int L1,int L2,int M1,int M2,int RG>
__device__ __forceinline__ void do_path(
    const float* __restrict__ gx1, const float* __restrict__ gx2,
    int wpo, const float* __restrict__ cg,
    uint32_t* sx2h, uint32_t* sA0, uint32_t* sA1, uint32_t sA0a, uint32_t sA1a,
    uint32_t* sW0, uint32_t* sW1, uint32_t sW0a, uint32_t sW1a,
    float (&acc)[L3][M3*RG/64][4/RG][4])
{
    constexpr int CGn=8/RG, CPW=M3/CGn, NC=CPW/8, R2=4/RG, WS=M3+8;
    constexpr int NCH=M1*M2/32, C=(M2/2)*L2;
    const int tid=threadIdx.x, wid=tid>>5, lane=tid&31;
    const int cgp=wid/RG, rowg=wid%RG, gID=lane>>2, tIG=lane&3;
    const int q=tid&15, bg=tid>>4;
    const int rbase=rowg*(64/RG)+(lane&7)+((lane>>3)&1)*8;
    const int qb=((lane>>4)&1)*16;

    __syncthreads();                 // prior path's MMA fully drained
    for(int idx=tid; idx<64*C; idx+=NT){
        int b=idx/C, c=idx-b*C, vp=c/L2, j=c-vp*L2;
        float lo=gx2[b*480+(2*vp)*L2+j], hi=gx2[b*480+(2*vp+1)*L2+j];
        sx2h[c*66+b]=pack2(lo,hi);
    }
    __syncthreads();

    float rx1[4][L1];
    auto loadx1=[&](int u){
#pragma unroll
        for(int it=0;it<4;++it)
#pragma unroll
            for(int i=0;i<L1;++i)
                rx1[it][i]=gx1[(it*16+bg)*480+u*L1+i];
    };
    auto stageW=[&](int n){          // cp.async: g_wp -> sW buffer
        const uint32_t sa=(n&1)?sW1a:sW0a;
        const uint32_t* g=g_wp+wpo+(size_t)n*16*M3;
        constexpr int CH=4*M3;       // 16B chunks
#pragma unroll
        for(int t2=0;t2<(CH+NT-1)/NT;++t2){
            int idx=t2*NT+tid;
            if(CH%NT==0 || idx<CH){
                int kp=idx/(M3/4), wq=idx-kp*(M3/4);
                asm volatile("cp.async.ca.shared.global [%0],[%1],16;"
                    ::"r"(sa+(kp*WS+4*wq)*4),"l"(g+(size_t)kp*M3+4*wq):"memory");
            }
        }
        asm volatile("cp.async.commit_group;":::"memory");
    };
    auto compP=[&](int n){
        uint32_t* d=(n&1)?sA1:sA0;
        const int vp0=((n*32)&(M2-1))>>1;
        const uint32_t* c2=sx2h+(vp0+q)*L2*66;
#pragma unroll
        for(int it=0;it<4;++it){
            const int b=it*16+bg;
            float2 cf[L2];
#pragma unroll
            for(int j=0;j<L2;++j){
                uint32_t cw=c2[j*66+b];
                cf[j]=__half22float2(*(__half2*)&cw);
            }
            float pa[L3], pb[L3];
#pragma unroll
            for(int k=0;k<L3;++k){ pa[k]=0.f; pb[k]=0.f; }
#pragma unroll
            for(int i=0;i<L1;++i){
                const float xi=rx1[it][i];
#pragma unroll
                for(int j=0;j<L2;++j){
                    float xa=xi*cf[j].x, xb=xi*cf[j].y;
#pragma unroll
                    for(int k=0;k<L3;++k){
                        float cc=cg[(i*L2+j)*L3+k];
                        pa[k]+=cc*xa; pb[k]+=cc*xb;
                    }
                }
            }
#pragma unroll
            for(int k=0;k<L3;++k) d[k*1280+b*20+q]=pack2(pa[k],pb[k]);
        }
    };

    loadx1(0); stageW(0); compP(0);
#pragma unroll 1
    for(int n=0;n<NCH;++n){
        asm volatile("cp.async.wait_group 0;":::"memory");
        __syncthreads();             // sA(n)+sW(n) ready; prev MMA done
        if(n+1<NCH) stageW(n+1);     // async into other buffer
        const uint32_t* sWc=(n&1)?sW1:sW0;
        uint32_t breg[2][NC][2];
#pragma unroll
        for(int ks=0;ks<2;++ks)
#pragma unroll
            for(int nc=0;nc<NC;++nc){
                const uint32_t* Bb=sWc+(ks*8+tIG)*WS+cgp*CPW+nc*8+gID;
                breg[ks][nc][0]=Bb[0]; breg[ks][nc][1]=Bb[4*WS];
            }
        const uint32_t sAa=(n&1)?sA1a:sA0a;
#pragma unroll
        for(int ks=0;ks<2;++ks){
            uint32_t a[L3][R2][4];
#pragma unroll
            for(int k=0;k<L3;++k)
#pragma unroll
                for(int r2=0;r2<R2;++r2)
                    LDSM4(a[k][r2], sAa+(k*1280+(rbase+r2*16)*20)*4+qb+ks*32);
#pragma unroll
            for(int k=0;k<L3;++k)
#pragma unroll
                for(int nc=0;nc<NC;++nc)
#pragma unroll
                    for(int r2=0;r2<R2;++r2)
                        mma16(acc[k][nc][r2],a[k][r2],breg[ks][nc]);
        }
        if(n+1<NCH){
            if((((n+1)*32)&(M2-1))==0) loadx1((n+1)*32/M2);
            compP(n+1);
        }
    }
}

template<int M3,int L3,int OFF3,int RG>
__device__ __forceinline__ void epilogue(float (&acc)[L3][M3*RG/64][4/RG][4],
    float* __restrict__ out,int tile,float coeff)
{
    constexpr int CGn=8/RG, CPW=M3/CGn, NC=CPW/8, R2=4/RG;
    const int tid=threadIdx.x, wid=tid>>5, lane=tid&31;
    const int cgp=wid/RG, rowg=wid%RG, gID=lane>>2, tIG=lane&3;
#pragma unroll
    for(int k=0;k<L3;++k)
#pragma unroll
        for(int nc=0;nc<NC;++nc)
#pragma unroll
            for(int r2=0;r2<R2;++r2){
                const int wc=cgp*CPW+nc*8+2*tIG;
                const int row=tile*64+rowg*(64/RG)+r2*16+gID;
                float* po=out+(size_t)row*480+OFF3;
                po[(wc+0)*L3+k]=coeff*acc[k][nc][r2][0];
                po[(wc+1)*L3+k]=coeff*acc[k][nc][r2][1];
                po+=8*480;
                po[(wc+0)*L3+k]=coeff*acc[k][nc][r2][2];
                po[(wc+1)*L3+k]=coeff*acc[k][nc][r2][3];
            }
}

__global__ void __launch_bounds__(NT,2)
tp_kernel(const float* __restrict__ x1,const float* __restrict__ x2,
          float* __restrict__ out,const __grid_constant__ TPParams P)
{
    extern __shared__ char sm[];
    float* scg=(float*)sm;
    for(int e=threadIdx.x;e<384;e+=NT) scg[e]=P.cg[e];
    const int tile=blockIdx.y;
    const float* X1=x1+(size_t)tile*64*480;
    const float* X2=x2+(size_t)tile*64*480;
    uint32_t* sx2h=(uint32_t*)(sm+OX2);

    if(blockIdx.x==0){
        uint32_t* A0=(uint32_t*)(sm+OSA); uint32_t* A1=(uint32_t*)(sm+OSA+5120);
        uint32_t* W0=(uint32_t*)(sm+OSA+10240); uint32_t* W1=(uint32_t*)(sm+OSA+10240+8704);
        uint32_t a0=smem_u32(A0),a1=smem_u32(A1),w0=smem_u32(W0),w1=smem_u32(W1);
        float acc[1][4][2][4]={};
        do_path<128,1,1,1,128,128,2>(X1,    X2,    P.wpo[0],scg+P.cgo[0],sx2h,A0,A1,a0,a1,W0,W1,w0,w1,acc);
        do_path<128,1,3,3, 64, 64,2>(X1+128,X2+128,P.wpo[4],scg+P.cgo[4],sx2h,A0,A1,a0,a1,W0,W1,w0,w1,acc);
        do_path<128,1,5,5, 32, 32,2>(X1+320,X2+320,P.wpo[9],scg+P.cgo[9],sx2h,A0,A1,a0,a1,W0,W1,w0,w1,acc);
        epilogue<128,1,0,2>(acc,out,tile,P.coeff[0]);
    } else if(blockIdx.x==1){
        uint32_t* A0=(uint32_t*)(sm+OSA); uint32_t* A1=(uint32_t*)(sm+OSA+15360);
        uint32_t* W0=(uint32_t*)(sm+OSA+30720); uint32_t* W1=(uint32_t*)(sm+OSA+30720+4608);
        uint32_t a0=smem_u32(A0),a1=smem_u32(A1),w0=smem_u32(W0),w1=smem_u32(W1);
        float acc[3][4][1][4]={};
        do_path<64,3,1,3,128, 64,4>(X1,    X2+128,P.wpo[1],scg+P.cgo[1],sx2h,A0,A1,a0,a1,W0,W1,w0,w1,acc);
        do_path<64,3,3,1, 64,128,4>(X1+128,X2,    P.wpo[3],scg+P.cgo[3],sx2h,A0,A1,a0,a1,W0,W1,w0,w1,acc);
        do_path<64,3,3,5, 64, 32,4>(X1+128,X2+320,P.wpo[6],scg+P.cgo[6],sx2h,A0,A1,a0,a1,W0,W1,w0,w1,acc);
        do_path<64,3,5,3, 32, 64,4>(X1+320,X2+128,P.wpo[8],scg+P.cgo[8],sx2h,A0,A1,a0,a1,W0,W1,w0,w1,acc);
        epilogue<64,3,128,4>(acc,out,tile,P.coeff[1]);
    } else {
        uint32_t* A0=(uint32_t*)(sm+OSA); uint32_t* A1=(uint32_t*)(sm+OSA+25600);
        uint32_t* W0=(uint32_t*)(sm+OSA+51200); uint32_t* W1=(uint32_t*)(sm+OSA+51200+2560);
        uint32_t a0=smem_u32(A0),a1=smem_u32(A1),w0=smem_u32(W0),w1=smem_u32(W1);
        float acc[5][2][1][4]={};
        do_path<32,5,1,5,128, 32,4>(X1,    X2+320,P.wpo[2], scg+P.cgo[2], sx2h,A0,A1,a0,a1,W0,W1,w0,w1,acc);
        do_path<32,5,3,3, 64, 64,4>(X1+128,X2+128,P.wpo[5], scg+P.cgo[5], sx2h,A0,A1,a0,a1,W0,W1,w0,w1,acc);
        do_path<32,5,5,1, 32,128,4>(X1+320,X2,    P.wpo[7], scg+P.cgo[7], sx2h,A0,A1,a0,a1,W0,W1,w0,w1,acc);
        do_path<32,5,5,5, 32, 32,4>(X1+320,X2+320,P.wpo[10],scg+P.cgo[10],sx2h,A0,A1,a0,a1,W0,W1,w0,w1,acc);
        epilogue<32,5,320,4>(acc,out,tile,P.coeff[2]);
    }
}

// ---------------------- host: CG construction (verified) --------------------

typedef std::complex<double> cpx;
static double fct(int n){double r=1.0;for(int i=2;i<=n;++i)r*=i;return r;}

static void change_basis(int l, cpx q[5][5]){
    for(int a=0;a<5;++a)for(int b=0;b<5;++b)q[a][b]=cpx(0,0);
    const double s2=1.0/std::sqrt(2.0);
    for(int m=-l;m<0;++m){ q[l+m][l-m]=cpx(s2,0); q[l+m][l+m]=cpx(0,-s2); }
    q[l][l]=cpx(1,0);
    for(int m=1;m<=l;++m){
        double sg=(m&1)?-1.0:1.0;
        q[l+m][l+m]=cpx(sg*s2,0); q[l+m][l-m]=cpx(0,sg*s2);
    }
    cpx ph(1,0);
    for(int t=0;t<l;++t)ph*=cpx(0,-1);
    for(int a=0;a<2*l+1;++a)for(int b=0;b<2*l+1;++b)q[a][b]*=ph;
}

static void real_cg(int l1,int l2,int l3,float outc[5][5][5]){
    cpx Q1[5][5],Q2[5][5],Q3[5][5];
    change_basis(l1,Q1); change_basis(l2,Q2); change_basis(l3,Q3);
    double C[5][5][5]; memset(C,0,sizeof(C));
    for(int m1=-l1;m1<=l1;++m1)
        for(int m2=-l2;m2<=l2;++m2){
            int m3=m1+m2;
            if(m3<-l3||m3>l3)continue;
            double pref=std::sqrt((2.0*l3+1.0)
                *fct(l3+l1-l2)*fct(l3-l1+l2)*fct(l1+l2-l3)/fct(l1+l2+l3+1)
                *fct(l3+m3)*fct(l3-m3)*fct(l1-m1)*fct(l1+m1)*fct(l2-m2)*fct(l2+m2));
            double s=0.0;
            for(int k=0;k<=l1+l2-l3;++k){
                if(l1-m1-k<0||l2+m2-k<0||l3-l2+m1+k<0||l3-l1-m2+k<0)continue;
                double d=fct(k)*fct(l1+l2-l3-k)*fct(l1-m1-k)
                        *fct(l2+m2-k)*fct(l3-l2+m1+k)*fct(l3-l1-m2+k);
                s+=((k&1)?-1.0:1.0)/d;
            }
            C[l1+m1][l2+m2][l3+m3]=pref*s;
        }
    int n1=2*l1+1,n2=2*l2+1,n3=2*l3+1;
    double Rr[5][5][5],nrm=0.0;
    for(int j=0;j<n1;++j)
        for(int lb=0;lb<n2;++lb)
            for(int nn=0;nn<n3;++nn){
                cpx a(0,0);
                for(int i=0;i<n1;++i)
                    for(int kk=0;kk<n2;++kk)
                        for(int m=0;m<n3;++m)
                            if(C[i][kk][m]!=0.0)
                                a+=Q1[i][j]*Q2[kk][lb]*Q3[m][nn]*C[i][kk][m];
                Rr[j][lb][nn]=a.real();
                nrm+=a.real()*a.real();
            }
    nrm=std::sqrt(nrm);
    for(int j=0;j<5;++j)for(int lb=0;lb<5;++lb)for(int nn=0;nn<5;++nn)
        outc[j][lb][nn]=(j<n1&&lb<n2&&nn<n3)?(float)(Rr[j][lb][nn]/nrm):0.f;
}

static void build_params(TPParams& P){
    memset(&P,0,sizeof(P));
    const int M_[3]={128,64,32}, L_[3]={0,1,2}, Pa[3]={1,-1,1};
    long long fan[3]={0,0,0};
    int woff=0, cgo=0, idx=0;
    for(int i1=0;i1<3;++i1)for(int i2=0;i2<3;++i2)for(int i3=0;i3<3;++i3){
        int l1=L_[i1],l2=L_[i2],l3=L_[i3];
        if(Pa[i1]*Pa[i2]!=Pa[i3])continue;
        if(l3<abs(l1-l2)||l3>l1+l2)continue;
        float C[5][5][5];
        real_cg(l1,l2,l3,C);
        P.woff[idx]=woff; P.cgo[idx]=cgo;
        P.wpo[idx]=woff/2; P.m3s[idx]=M_[i3];
        int n1=2*l1+1,n2=2*l2+1,n3=2*l3+1;
        for(int i=0;i<n1;++i)for(int j=0;j<n2;++j)for(int k=0;k<n3;++k)
            P.cg[cgo++]=C[i][j][k];
        woff+=M_[i1]*M_[i2]*M_[i3];
        fan[i3]+=(long long)M_[i1]*M_[i2];
        ++idx;
    }
    P.wpo[11]=woff/2;
    for(int t=0;t<3;++t)
        P.coeff[t]=(float)std::sqrt((double)(2*L_[t]+1)/(double)fan[t]);
}

// ------------------------------ entry ---------------------------------------

extern "C" void kernel_launch(void* const* d_in, const int* in_sizes, int n_in,
                              void* d_out, int out_size) {
    TPParams P;
    build_params(P);
    wpre_kernel<<<(P.wpo[11]+255)/256, 256>>>((const float*)d_in[2], P);
    cudaFuncSetAttribute(tp_kernel, cudaFuncAttributeMaxDynamicSharedMemorySize, SMT);
    tp_kernel<<<dim3(3,128), NT, SMT>>>(
        (const float*)d_in[0], (const float*)d_in[1], (float*)d_out, P);
}

// round 12
// speedup vs baseline: 1.3973x; 1.1478x over previous
#include <cuda_runtime.h>
#include <cuda_fp16.h>
#include <cstdint>
#include <cmath>
#include <cstring>
#include <complex>
#include <cstdlib>

#define NT 256
struct TPParams {
    float cg[384]; float coeff[3];
    int cgo[12], woff[12], wpo[12], m3s[12];
};

__device__ uint32_t g_wp[2244608];   // W half2, layout [path][chunk][w][perm(kpair)]

// smem: cg[0:1536) | sx2h[1536:26880) | variant arena from 26880
#define OX2 1536
#define OAR 26880
#define SMT 82176

__device__ __forceinline__ uint32_t pack2(float lo, float hi){
    uint32_t r; asm("cvt.rn.f16x2.f32 %0,%1,%2;":"=r"(r):"f"(hi),"f"(lo)); return r;
}
__device__ __forceinline__ uint32_t hmul2u(uint32_t a, uint32_t b){
    uint32_t r; asm("mul.rn.f16x2 %0,%1,%2;":"=r"(r):"r"(a),"r"(b)); return r;
}
__device__ __forceinline__ uint32_t smem_u32(const void* p){
    uint32_t a;
    asm("{ .reg .u64 t; cvta.to.shared.u64 t, %1; cvt.u32.u64 %0, t; }":"=r"(a):"l"(p));
    return a;
}
__device__ __forceinline__ void mma16(float* d,const uint32_t* a,const uint32_t* b){
    asm volatile("mma.sync.aligned.m16n8k16.row.col.f32.f16.f16.f32 "
        "{%0,%1,%2,%3},{%4,%5,%6,%7},{%8,%9},{%0,%1,%2,%3};"
        :"+f"(d[0]),"+f"(d[1]),"+f"(d[2]),"+f"(d[3])
        :"r"(a[0]),"r"(a[1]),"r"(a[2]),"r"(a[3]),"r"(b[0]),"r"(b[1]));
}
#define LDSM4(r,addr) asm volatile( \
    "ldmatrix.sync.aligned.m8n8.x4.shared.b16 {%0,%1,%2,%3},[%4];" \
    :"=r"((r)[0]),"=r"((r)[1]),"=r"((r)[2]),"=r"((r)[3]):"r"(addr))
#define CPA(sa,g) asm volatile("cp.async.ca.shared.global [%0],[%1],16;"::"r"(sa),"l"(g):"memory")
#define CPC() asm volatile("cp.async.commit_group;":::"memory")
#define CPW0() asm volatile("cp.async.wait_group 0;":::"memory")

// ---- W prepass: [path][chunk n][w][pos], pos=perm(p)= (p%4)*4+p/4 (self-inverse)
__global__ void wpre_kernel(const float* __restrict__ w,
                            const __grid_constant__ TPParams P){
    int r = blockIdx.x*256 + threadIdx.x;
    if(r >= P.wpo[11]) return;
    int t = 0;
    while(r >= P.wpo[t+1]) ++t;
    int loc = r - P.wpo[t], M3 = P.m3s[t];
    int n = loc/(16*M3), rem = loc - n*16*M3, w_ = rem>>4, pos = rem&15;
    int p = ((pos&3)<<2) + (pos>>2);
    const float* s = w + P.woff[t] + (size_t)(n*32 + 2*p)*M3 + w_;
    g_wp[r] = pack2(s[0], s[M3]);
}

// ---- specialized path (1,1,1): A-fragments in registers --------------------
__device__ __forceinline__ void path000(
    const float* __restrict__ gx1, const float* __restrict__ gx2, int wpo,
    uint32_t* sx2t, uint32_t* sW0, uint32_t* sW1, uint32_t sW0a, uint32_t sW1a,
    float (&acc)[1][4][2][4])
{
    const int tid=threadIdx.x, wid=tid>>5, lane=tid&31;
    const int cgp=wid>>1, rowg=wid&1, gID=lane>>2, tIG=lane&3;
    __syncthreads();
    for(int idx=tid; idx<4096; idx+=NT){
        int cgr=idx>>10, rem=idx&1023, b=rem>>4, pos=rem&15;
        int p=((pos&3)<<2)+(pos>>2), v=cgr*32+2*p;
        sx2t[idx]=pack2(gx2[b*480+v], gx2[b*480+v+1]);
    }
    uint32_t x1h[2][2];
    auto ldx1=[&](int u){
#pragma unroll
        for(int r2=0;r2<2;++r2)
#pragma unroll
            for(int h=0;h<2;++h){
                float v=gx1[(rowg*32+r2*16+gID+h*8)*480+u];
                x1h[r2][h]=pack2(v,v);
            }
    };
    auto stW=[&](int n){
        uint32_t sa=(n&1)?sW1a:sW0a;
        const uint4* g=(const uint4*)(g_wp+wpo+(size_t)n*2048);
#pragma unroll
        for(int t2=0;t2<2;++t2) CPA(sa+(t2*NT+tid)*16, g+t2*NT+tid);
        CPC();
    };
    ldx1(0); stW(0);
#pragma unroll 1
    for(int n=0;n<512;++n){
        CPW0(); __syncthreads();
        if(n+1<512) stW(n+1);
        const uint32_t* sWc=(n&1)?sW1:sW0;
        uint32_t breg[2][4][2];
#pragma unroll
        for(int nc=0;nc<4;++nc){
            uint4 v=((const uint4*)sWc)[(cgp*32+nc*8+gID)*4+tIG];
            breg[0][nc][0]=v.x; breg[0][nc][1]=v.y;
            breg[1][nc][0]=v.z; breg[1][nc][1]=v.w;
        }
        const int cgr=n&3;
        uint32_t a[2][2][4];
#pragma unroll
        for(int r2=0;r2<2;++r2){
            const uint32_t* base=sx2t+cgr*1024+(rowg*32+r2*16+gID)*16+tIG*4;
            uint4 v0=*(const uint4*)base;
            uint4 v1=*(const uint4*)(base+128);   // +8 rows * 16
            a[0][r2][0]=hmul2u(v0.x,x1h[r2][0]); a[0][r2][1]=hmul2u(v1.x,x1h[r2][1]);
            a[0][r2][2]=hmul2u(v0.y,x1h[r2][0]); a[0][r2][3]=hmul2u(v1.y,x1h[r2][1]);
            a[1][r2][0]=hmul2u(v0.z,x1h[r2][0]); a[1][r2][1]=hmul2u(v1.z,x1h[r2][1]);
            a[1][r2][2]=hmul2u(v0.w,x1h[r2][0]); a[1][r2][3]=hmul2u(v1.w,x1h[r2][1]);
        }
#pragma unroll
        for(int ks=0;ks<2;++ks)
#pragma unroll
            for(int nc=0;nc<4;++nc)
#pragma unroll
                for(int r2=0;r2<2;++r2)
                    mma16(acc[0][nc][r2],a[ks][r2],breg[ks][nc]);
        if((n&3)==3 && n+1<512) ldx1((n+1)>>2);
    }
}

// ---- generic fused path ----------------------------------------------------
template<int M3,int L3,int L1,int L2,int M1,int M2,int RG>
__device__ __forceinline__ void do_path(
    const float* __restrict__ gx1, const float* __restrict__ gx2,
    int wpo, const float* __restrict__ cg,
    uint32_t* sx2h, uint32_t* sA0, uint32_t* sA1, uint32_t sA0a, uint32_t sA1a,
    uint32_t* sW0, uint32_t* sW1, uint32_t sW0a, uint32_t sW1a,
    float (&acc)[L3][M3*RG/64][4/RG][4])
{
    constexpr int CGn=8/RG, CPW=M3/CGn, NC=CPW/8, R2=4/RG;
    constexpr int NCH=M1*M2/32, C=(M2/2)*L2, CH4=4*M3;
    const int tid=threadIdx.x, wid=tid>>5, lane=tid&31;
    const int cgp=wid/RG, rowg=wid%RG, gID=lane>>2, tIG=lane&3;
    const int q=tid&15, bg=tid>>4;
    const int rbase=rowg*(64/RG)+(lane&7)+((lane>>3)&1)*8;
    const int qb=((lane>>4)&1)*16;

    __syncthreads();
    for(int idx=tid; idx<64*C; idx+=NT){
        int b=idx/C, c=idx-b*C, vp=c/L2, j=c-vp*L2;
        float lo=gx2[b*480+(2*vp)*L2+j], hi=gx2[b*480+(2*vp+1)*L2+j];
        sx2h[c*66+b]=pack2(lo,hi);
    }
    __syncthreads();

    float rx1[4][L1];
    auto loadx1=[&](int u){
#pragma unroll
        for(int it=0;it<4;++it)
#pragma unroll
            for(int i=0;i<L1;++i)
                rx1[it][i]=gx1[(it*16+bg)*480+u*L1+i];
    };
    auto stageW=[&](int n){
        const uint32_t sa=(n&1)?sW1a:sW0a;
        const uint4* g=(const uint4*)(g_wp+wpo+(size_t)n*16*M3);
#pragma unroll
        for(int t2=0;t2<(CH4+NT-1)/NT;++t2){
            int idx=t2*NT+tid;
            if(CH4%NT==0 || idx<CH4) CPA(sa+idx*16, g+idx);
        }
        CPC();
    };
    auto compP=[&](int n){
        uint32_t* d=(n&1)?sA1:sA0;
        const int vp0=((n*32)&(M2-1))>>1;
        const uint32_t* c2=sx2h+(vp0+q)*L2*66;
#pragma unroll
        for(int it=0;it<4;++it){
            const int b=it*16+bg;
            float2 cf[L2];
#pragma unroll
            for(int j=0;j<L2;++j){
                uint32_t cw=c2[j*66+b];
                cf[j]=__half22float2(*(__half2*)&cw);
            }
            float pa[L3], pb[L3];
#pragma unroll
            for(int k=0;k<L3;++k){ pa[k]=0.f; pb[k]=0.f; }
#pragma unroll
            for(int i=0;i<L1;++i){
                const float xi=rx1[it][i];
#pragma unroll
                for(int j=0;j<L2;++j){
                    float xa=xi*cf[j].x, xb=xi*cf[j].y;
#pragma unroll
                    for(int k=0;k<L3;++k){
                        float cc=cg[(i*L2+j)*L3+k];
                        pa[k]+=cc*xa; pb[k]+=cc*xb;
                    }
                }
            }
#pragma unroll
            for(int k=0;k<L3;++k) d[k*1280+b*20+q]=pack2(pa[k],pb[k]);
        }
    };

    loadx1(0); stageW(0); compP(0);
#pragma unroll 1
    for(int n=0;n<NCH;++n){
        CPW0(); __syncthreads();
        if(n+1<NCH) stageW(n+1);
        const uint32_t* sWc=(n&1)?sW1:sW0;
        uint32_t breg[2][NC][2];
#pragma unroll
        for(int nc=0;nc<NC;++nc){
            uint4 v=((const uint4*)sWc)[(cgp*CPW+nc*8+gID)*4+tIG];
            breg[0][nc][0]=v.x; breg[0][nc][1]=v.y;
            breg[1][nc][0]=v.z; breg[1][nc][1]=v.w;
        }
        const uint32_t sAa=(n&1)?sA1a:sA0a;
#pragma unroll
        for(int ks=0;ks<2;++ks){
            uint32_t a[L3][R2][4];
#pragma unroll
            for(int k=0;k<L3;++k)
#pragma unroll
                for(int r2=0;r2<R2;++r2)
                    LDSM4(a[k][r2], sAa+(k*1280+(rbase+r2*16)*20)*4+qb+ks*32);
#pragma unroll
            for(int k=0;k<L3;++k)
#pragma unroll
                for(int nc=0;nc<NC;++nc)
#pragma unroll
                    for(int r2=0;r2<R2;++r2)
                        mma16(acc[k][nc][r2],a[k][r2],breg[ks][nc]);
        }
        if(n+1<NCH){
            if((((n+1)*32)&(M2-1))==0) loadx1((n+1)*32/M2);
            compP(n+1);
        }
    }
}

template<int M3,int L3,int OFF3,int RG>
__device__ __forceinline__ void epilogue(float (&acc)[L3][M3*RG/64][4/RG][4],
    float* __restrict__ out,int tile,float coeff)
{
    constexpr int CGn=8/RG, CPW=M3/CGn, NC=CPW/8, R2=4/RG;
    const int tid=threadIdx.x, wid=tid>>5, lane=tid&31;
    const int cgp=wid/RG, rowg=wid%RG, gID=lane>>2, tIG=lane&3;
#pragma unroll
    for(int k=0;k<L3;++k)
#pragma unroll
        for(int nc=0;nc<NC;++nc)
#pragma unroll
            for(int r2=0;r2<R2;++r2){
                const int wc=cgp*CPW+nc*8+2*tIG;
                const int row=tile*64+rowg*(64/RG)+r2*16+gID;
                float* po=out+(size_t)row*480+OFF3;
                po[(wc+0)*L3+k]=coeff*acc[k][nc][r2][0];
                po[(wc+1)*L3+k]=coeff*acc[k][nc][r2][1];
                po+=8*480;
                po[(wc+0)*L3+k]=coeff*acc[k][nc][r2][2];
                po[(wc+1)*L3+k]=coeff*acc[k][nc][r2][3];
            }
}

__global__ void __launch_bounds__(NT,2)
tp_kernel(const float* __restrict__ x1,const float* __restrict__ x2,
          float* __restrict__ out,const __grid_constant__ TPParams P)
{
    extern __shared__ char sm[];
    float* scg=(float*)sm;
    for(int e=threadIdx.x;e<384;e+=NT) scg[e]=P.cg[e];
    const int tile=blockIdx.y;
    const float* X1=x1+(size_t)tile*64*480;
    const float* X2=x2+(size_t)tile*64*480;
    uint32_t* sx2h=(uint32_t*)(sm+OX2);

    if(blockIdx.x==0){
        uint32_t* T2=(uint32_t*)(sm+OAR);                  // 16384
        uint32_t* A0=(uint32_t*)(sm+OAR+16384);            // 5120
        uint32_t* A1=(uint32_t*)(sm+OAR+21504);
        uint32_t* W0=(uint32_t*)(sm+OAR+26624);            // 8192
        uint32_t* W1=(uint32_t*)(sm+OAR+34816);
        uint32_t a0=smem_u32(A0),a1=smem_u32(A1),w0=smem_u32(W0),w1=smem_u32(W1);
        float acc[1][4][2][4]={};
        path000(X1, X2, P.wpo[0], T2, W0, W1, w0, w1, acc);
        do_path<128,1,3,3, 64, 64,2>(X1+128,X2+128,P.wpo[4],scg+P.cgo[4],sx2h,A0,A1,a0,a1,W0,W1,w0,w1,acc);
        do_path<128,1,5,5, 32, 32,2>(X1+320,X2+320,P.wpo[9],scg+P.cgo[9],sx2h,A0,A1,a0,a1,W0,W1,w0,w1,acc);
        epilogue<128,1,0,2>(acc,out,tile,P.coeff[0]);
    } else if(blockIdx.x==1){
        uint32_t* A0=(uint32_t*)(sm+OAR);                  // 15360
        uint32_t* A1=(uint32_t*)(sm+OAR+15360);
        uint32_t* W0=(uint32_t*)(sm+OAR+30720);            // 4096
        uint32_t* W1=(uint32_t*)(sm+OAR+34816);
        uint32_t a0=smem_u32(A0),a1=smem_u32(A1),w0=smem_u32(W0),w1=smem_u32(W1);
        float acc[3][4][1][4]={};
        do_path<64,3,1,3,128, 64,4>(X1,    X2+128,P.wpo[1],scg+P.cgo[1],sx2h,A0,A1,a0,a1,W0,W1,w0,w1,acc);
        do_path<64,3,3,1, 64,128,4>(X1+128,X2,    P.wpo[3],scg+P.cgo[3],sx2h,A0,A1,a0,a1,W0,W1,w0,w1,acc);
        do_path<64,3,3,5, 64, 32,4>(X1+128,X2+320,P.wpo[6],scg+P.cgo[6],sx2h,A0,A1,a0,a1,W0,W1,w0,w1,acc);
        do_path<64,3,5,3, 32, 64,4>(X1+320,X2+128,P.wpo[8],scg+P.cgo[8],sx2h,A0,A1,a0,a1,W0,W1,w0,w1,acc);
        epilogue<64,3,128,4>(acc,out,tile,P.coeff[1]);
    } else {
        uint32_t* A0=(uint32_t*)(sm+OAR);                  // 25600
        uint32_t* A1=(uint32_t*)(sm+OAR+25600);
        uint32_t* W0=(uint32_t*)(sm+OAR+51200);            // 2048
        uint32_t* W1=(uint32_t*)(sm+OAR+53248);
        uint32_t a0=smem_u32(A0),a1=smem_u32(A1),w0=smem_u32(W0),w1=smem_u32(W1);
        float acc[5][2][1][4]={};
        do_path<32,5,1,5,128, 32,4>(X1,    X2+320,P.wpo[2], scg+P.cgo[2], sx2h,A0,A1,a0,a1,W0,W1,w0,w1,acc);
        do_path<32,5,3,3, 64, 64,4>(X1+128,X2+128,P.wpo[5], scg+P.cgo[5], sx2h,A0,A1,a0,a1,W0,W1,w0,w1,acc);
        do_path<32,5,5,1, 32,128,4>(X1+320,X2,    P.wpo[7], scg+P.cgo[7], sx2h,A0,A1,a0,a1,W0,W1,w0,w1,acc);
        do_path<32,5,5,5, 32, 32,4>(X1+320,X2+320,P.wpo[10],scg+P.cgo[10],sx2h,A0,A1,a0,a1,W0,W1,w0,w1,acc);
        epilogue<32,5,320,4>(acc,out,tile,P.coeff[2]);
    }
}

// ---------------------- host: CG construction (verified) --------------------

typedef std::complex<double> cpx;
static double fct(int n){double r=1.0;for(int i=2;i<=n;++i)r*=i;return r;}

static void change_basis(int l, cpx q[5][5]){
    for(int a=0;a<5;++a)for(int b=0;b<5;++b)q[a][b]=cpx(0,0);
    const double s2=1.0/std::sqrt(2.0);
    for(int m=-l;m<0;++m){ q[l+m][l-m]=cpx(s2,0); q[l+m][l+m]=cpx(0,-s2); }
    q[l][l]=cpx(1,0);
    for(int m=1;m<=l;++m){
        double sg=(m&1)?-1.0:1.0;
        q[l+m][l+m]=cpx(sg*s2,0); q[l+m][l-m]=cpx(0,sg*s2);
    }
    cpx ph(1,0);
    for(int t=0;t<l;++t)ph*=cpx(0,-1);
    for(int a=0;a<2*l+1;++a)for(int b=0;b<2*l+1;++b)q[a][b]*=ph;
}

static void real_cg(int l1,int l2,int l3,float outc[5][5][5]){
    cpx Q1[5][5],Q2[5][5],Q3[5][5];
    change_basis(l1,Q1); change_basis(l2,Q2); change_basis(l3,Q3);
    double C[5][5][5]; memset(C,0,sizeof(C));
    for(int m1=-l1;m1<=l1;++m1)
        for(int m2=-l2;m2<=l2;++m2){
            int m3=m1+m2;
            if(m3<-l3||m3>l3)continue;
            double pref=std::sqrt((2.0*l3+1.0)
                *fct(l3+l1-l2)*fct(l3-l1+l2)*fct(l1+l2-l3)/fct(l1+l2+l3+1)
                *fct(l3+m3)*fct(l3-m3)*fct(l1-m1)*fct(l1+m1)*fct(l2-m2)*fct(l2+m2));
            double s=0.0;
            for(int k=0;k<=l1+l2-l3;++k){
                if(l1-m1-k<0||l2+m2-k<0||l3-l2+m1+k<0||l3-l1-m2+k<0)continue;
                double d=fct(k)*fct(l1+l2-l3-k)*fct(l1-m1-k)
                        *fct(l2+m2-k)*fct(l3-l2+m1+k)*fct(l3-l1-m2+k);
                s+=((k&1)?-1.0:1.0)/d;
            }
            C[l1+m1][l2+m2][l3+m3]=pref*s;
        }
    int n1=2*l1+1,n2=2*l2+1,n3=2*l3+1;
    double Rr[5][5][5],nrm=0.0;
    for(int j=0;j<n1;++j)
        for(int lb=0;lb<n2;++lb)
            for(int nn=0;nn<n3;++nn){
                cpx a(0,0);
                for(int i=0;i<n1;++i)
                    for(int kk=0;kk<n2;++kk)
                        for(int m=0;m<n3;++m)
                            if(C[i][kk][m]!=0.0)
                                a+=Q1[i][j]*Q2[kk][lb]*Q3[m][nn]*C[i][kk][m];
                Rr[j][lb][nn]=a.real();
                nrm+=a.real()*a.real();
            }
    nrm=std::sqrt(nrm);
    for(int j=0;j<5;++j)for(int lb=0;lb<5;++lb)for(int nn=0;nn<5;++nn)
        outc[j][lb][nn]=(j<n1&&lb<n2&&nn<n3)?(float)(Rr[j][lb][nn]/nrm):0.f;
}

static void build_params(TPParams& P){
    memset(&P,0,sizeof(P));
    const int M_[3]={128,64,32}, L_[3]={0,1,2}, Pa[3]={1,-1,1};
    long long fan[3]={0,0,0};
    int woff=0, cgo=0, idx=0;
    for(int i1=0;i1<3;++i1)for(int i2=0;i2<3;++i2)for(int i3=0;i3<3;++i3){
        int l1=L_[i1],l2=L_[i2],l3=L_[i3];
        if(Pa[i1]*Pa[i2]!=Pa[i3])continue;
        if(l3<abs(l1-l2)||l3>l1+l2)continue;
        float C[5][5][5];
        real_cg(l1,l2,l3,C);
        P.woff[idx]=woff; P.cgo[idx]=cgo;
        P.wpo[idx]=woff/2; P.m3s[idx]=M_[i3];
        int n1=2*l1+1,n2=2*l2+1,n3=2*l3+1;
        for(int i=0;i<n1;++i)for(int j=0;j<n2;++j)for(int k=0;k<n3;++k)
            P.cg[cgo++]=C[i][j][k];
        woff+=M_[i1]*M_[i2]*M_[i3];
        fan[i3]+=(long long)M_[i1]*M_[i2];
        ++idx;
    }
    P.wpo[11]=woff/2;
    for(int t=0;t<3;++t)
        P.coeff[t]=(float)std::sqrt((double)(2*L_[t]+1)/(double)fan[t]);
}

// ------------------------------ entry ---------------------------------------

extern "C" void kernel_launch(void* const* d_in, const int* in_sizes, int n_in,
                              void* d_out, int out_size) {
    TPParams P;
    build_params(P);
    wpre_kernel<<<(P.wpo[11]+255)/256, 256>>>((const float*)d_in[2], P);
    cudaFuncSetAttribute(tp_kernel, cudaFuncAttributeMaxDynamicSharedMemorySize, SMT);
    tp_kernel<<<dim3(3,128), NT, SMT>>>(
        (const float*)d_in[0], (const float*)d_in[1], (float*)d_out, P);
}

// round 13
// speedup vs baseline: 1.4523x; 1.0394x over previous
#include <cuda_runtime.h>
#include <cuda_fp16.h>
#include <cstdint>
#include <cmath>
#include <cstring>
#include <complex>
#include <cstdlib>

#define NT 256
struct TPParams {
    float cg[384]; float coeff[3];
    int cgo[12], woff[12], wpo[12], m3s[12];
};

__device__ uint32_t g_wp[2244608];   // W half2, [path][chunk'][w][perm(kpair)]

// smem: cg[0:1536) | sx2h[1536:26880) | variant arena from 26880
#define OX2 1536
#define OAR 26880
#define SMT 102656

__device__ __forceinline__ uint32_t pack2(float lo, float hi){
    uint32_t r; asm("cvt.rn.f16x2.f32 %0,%1,%2;":"=r"(r):"f"(hi),"f"(lo)); return r;
}
__device__ __forceinline__ uint32_t hmul2u(uint32_t a, uint32_t b){
    uint32_t r; asm("mul.rn.f16x2 %0,%1,%2;":"=r"(r):"r"(a),"r"(b)); return r;
}
__device__ __forceinline__ uint32_t smem_u32(const void* p){
    uint32_t a;
    asm("{ .reg .u64 t; cvta.to.shared.u64 t, %1; cvt.u32.u64 %0, t; }":"=r"(a):"l"(p));
    return a;
}
__device__ __forceinline__ void mma16(float* d,const uint32_t* a,const uint32_t* b){
    asm volatile("mma.sync.aligned.m16n8k16.row.col.f32.f16.f16.f32 "
        "{%0,%1,%2,%3},{%4,%5,%6,%7},{%8,%9},{%0,%1,%2,%3};"
        :"+f"(d[0]),"+f"(d[1]),"+f"(d[2]),"+f"(d[3])
        :"r"(a[0]),"r"(a[1]),"r"(a[2]),"r"(a[3]),"r"(b[0]),"r"(b[1]));
}
#define LDSM4(r,addr) asm volatile( \
    "ldmatrix.sync.aligned.m8n8.x4.shared.b16 {%0,%1,%2,%3},[%4];" \
    :"=r"((r)[0]),"=r"((r)[1]),"=r"((r)[2]),"=r"((r)[3]):"r"(addr))
#define CPA(sa,g) asm volatile("cp.async.ca.shared.global [%0],[%1],16;"::"r"(sa),"l"(g):"memory")
#define CPC() asm volatile("cp.async.commit_group;":::"memory")
#define CPW0() asm volatile("cp.async.wait_group 0;":::"memory")

// ---- W prepass: pos=perm(p); path 0 additionally cgr-major chunk order -----
__global__ void wpre_kernel(const float* __restrict__ w,
                            const __grid_constant__ TPParams P){
    int r = blockIdx.x*256 + threadIdx.x;
    if(r >= P.wpo[11]) return;
    int t = 0;
    while(r >= P.wpo[t+1]) ++t;
    int loc = r - P.wpo[t], M3 = P.m3s[t];
    int n = loc/(16*M3), rem = loc - n*16*M3, w_ = rem>>4, pos = rem&15;
    int p = ((pos&3)<<2) + (pos>>2);
    int nl = (t==0) ? ((n&127)*4 + (n>>7)) : n;   // storage n' -> logical n
    const float* s = w + P.woff[t] + (size_t)(nl*32 + 2*p)*M3 + w_;
    g_wp[r] = pack2(s[0], s[M3]);
}

// ---- specialized path (1,1,1): cgr-outer, A built from registers ----------
__device__ __forceinline__ void path000(
    const float* __restrict__ gx1, const float* __restrict__ gx2, int wpo,
    uint32_t* sx2t, uint32_t* x1s,
    uint32_t* sW0, uint32_t* sW1, uint32_t sW0a, uint32_t sW1a,
    float (&acc)[1][4][2][4])
{
    const int tid=threadIdx.x, wid=tid>>5, lane=tid&31;
    const int cgp=wid>>1, rowg=wid&1, gID=lane>>2, tIG=lane&3;
    __syncthreads();
    // stage x2 tile [cgr][b][perm(vpair)] as half2
    for(int idx=tid; idx<4096; idx+=NT){
        int cgr=idx>>10, rem=idx&1023, b=rem>>4, pos=rem&15;
        int p=((pos&3)<<2)+(pos>>2), v=cgr*32+2*p;
        sx2t[idx]=pack2(gx2[b*480+v], gx2[b*480+v+1]);
    }
    // stage x1 as duplicated half2: x1s[u*64+row]
    for(int idx=tid; idx<8192; idx+=NT){
        int u=idx>>6, row=idx&63;
        float v=gx1[row*480+u];
        x1s[idx]=pack2(v,v);
    }
    auto stW=[&](int n){
        uint32_t sa=(n&1)?sW1a:sW0a;
        const uint4* g=(const uint4*)(g_wp+wpo+(size_t)n*2048);
#pragma unroll
        for(int t2=0;t2<2;++t2) CPA(sa+(t2*NT+tid)*16, g+t2*NT+tid);
        CPC();
    };
    stW(0);
    __syncthreads();                      // staging of sx2t/x1s visible
#pragma unroll 1
    for(int cgr=0;cgr<4;++cgr){
        // loop-invariant x2 fragments for this cgr (held in registers)
        uint4 xv0[2], xv1[2];
#pragma unroll
        for(int r2=0;r2<2;++r2){
            const uint32_t* base=sx2t+cgr*1024+(rowg*32+r2*16+gID)*16+tIG*4;
            xv0[r2]=*(const uint4*)base;
            xv1[r2]=*(const uint4*)(base+128);
        }
#pragma unroll 1
        for(int u=0;u<128;++u){
            const int n=cgr*128+u;
            CPW0(); __syncthreads();
            if(n+1<512) stW(n+1);
            const uint32_t* sWc=(n&1)?sW1:sW0;
            uint32_t breg[2][4][2];
#pragma unroll
            for(int nc=0;nc<4;++nc){
                uint4 v=((const uint4*)sWc)[(cgp*32+nc*8+gID)*4+tIG];
                breg[0][nc][0]=v.x; breg[0][nc][1]=v.y;
                breg[1][nc][0]=v.z; breg[1][nc][1]=v.w;
            }
            uint32_t x1h[2][2];
#pragma unroll
            for(int r2=0;r2<2;++r2)
#pragma unroll
                for(int h=0;h<2;++h)
                    x1h[r2][h]=x1s[u*64+rowg*32+r2*16+gID+h*8];
#pragma unroll
            for(int ks=0;ks<2;++ks){
                uint32_t a[2][4];
#pragma unroll
                for(int r2=0;r2<2;++r2){
                    uint32_t s0=ks?xv0[r2].z:xv0[r2].x, s1=ks?xv1[r2].z:xv1[r2].x;
                    uint32_t s2=ks?xv0[r2].w:xv0[r2].y, s3=ks?xv1[r2].w:xv1[r2].y;
                    a[r2][0]=hmul2u(s0,x1h[r2][0]); a[r2][1]=hmul2u(s1,x1h[r2][1]);
                    a[r2][2]=hmul2u(s2,x1h[r2][0]); a[r2][3]=hmul2u(s3,x1h[r2][1]);
                }
#pragma unroll
                for(int nc=0;nc<4;++nc)
#pragma unroll
                    for(int r2=0;r2<2;++r2)
                        mma16(acc[0][nc][r2],a[r2],breg[ks][nc]);
            }
        }
    }
}

// ---- generic fused path ----------------------------------------------------
template<int M3,int L3,int L1,int L2,int M1,int M2,int RG>
__device__ __forceinline__ void do_path(
    const float* __restrict__ gx1, const float* __restrict__ gx2,
    int wpo, const float* __restrict__ cg,
    uint32_t* sx2h, uint32_t* sA0, uint32_t* sA1, uint32_t sA0a, uint32_t sA1a,
    uint32_t* sW0, uint32_t* sW1, uint32_t sW0a, uint32_t sW1a,
    float (&acc)[L3][M3*RG/64][4/RG][4])
{
    constexpr int CGn=8/RG, CPW=M3/CGn, NC=CPW/8, R2=4/RG;
    constexpr int NCH=M1*M2/32, C=(M2/2)*L2, CH4=4*M3;
    const int tid=threadIdx.x, wid=tid>>5, lane=tid&31;
    const int cgp=wid/RG, rowg=wid%RG, gID=lane>>2, tIG=lane&3;
    const int q=tid&15, bg=tid>>4;
    const int rbase=rowg*(64/RG)+(lane&7)+((lane>>3)&1)*8;
    const int qb=((lane>>4)&1)*16;

    __syncthreads();
    for(int idx=tid; idx<64*C; idx+=NT){
        int b=idx/C, c=idx-b*C, vp=c/L2, j=c-vp*L2;
        float lo=gx2[b*480+(2*vp)*L2+j], hi=gx2[b*480+(2*vp+1)*L2+j];
        sx2h[c*66+b]=pack2(lo,hi);
    }
    __syncthreads();

    float rx1[4][L1];
    auto loadx1=[&](int u){
#pragma unroll
        for(int it=0;it<4;++it)
#pragma unroll
            for(int i=0;i<L1;++i)
                rx1[it][i]=gx1[(it*16+bg)*480+u*L1+i];
    };
    auto stageW=[&](int n){
        const uint32_t sa=(n&1)?sW1a:sW0a;
        const uint4* g=(const uint4*)(g_wp+wpo+(size_t)n*16*M3);
#pragma unroll
        for(int t2=0;t2<(CH4+NT-1)/NT;++t2){
            int idx=t2*NT+tid;
            if(CH4%NT==0 || idx<CH4) CPA(sa+idx*16, g+idx);
        }
        CPC();
    };
    auto compP=[&](int n){
        uint32_t* d=(n&1)?sA1:sA0;
        const int vp0=((n*32)&(M2-1))>>1;
        const uint32_t* c2=sx2h+(vp0+q)*L2*66;
#pragma unroll
        for(int it=0;it<4;++it){
            const int b=it*16+bg;
            float2 cf[L2];
#pragma unroll
            for(int j=0;j<L2;++j){
                uint32_t cw=c2[j*66+b];
                cf[j]=__half22float2(*(__half2*)&cw);
            }
            float pa[L3], pb[L3];
#pragma unroll
            for(int k=0;k<L3;++k){ pa[k]=0.f; pb[k]=0.f; }
#pragma unroll
            for(int i=0;i<L1;++i){
                const float xi=rx1[it][i];
#pragma unroll
                for(int j=0;j<L2;++j){
                    float xa=xi*cf[j].x, xb=xi*cf[j].y;
#pragma unroll
                    for(int k=0;k<L3;++k){
                        float cc=cg[(i*L2+j)*L3+k];
                        pa[k]+=cc*xa; pb[k]+=cc*xb;
                    }
                }
            }
#pragma unroll
            for(int k=0;k<L3;++k) d[k*1280+b*20+q]=pack2(pa[k],pb[k]);
        }
    };

    loadx1(0); stageW(0); compP(0);
#pragma unroll 1
    for(int n=0;n<NCH;++n){
        CPW0(); __syncthreads();
        if(n+1<NCH) stageW(n+1);
        const uint32_t* sWc=(n&1)?sW1:sW0;
        uint32_t breg[2][NC][2];
#pragma unroll
        for(int nc=0;nc<NC;++nc){
            uint4 v=((const uint4*)sWc)[(cgp*CPW+nc*8+gID)*4+tIG];
            breg[0][nc][0]=v.x; breg[0][nc][1]=v.y;
            breg[1][nc][0]=v.z; breg[1][nc][1]=v.w;
        }
        const uint32_t sAa=(n&1)?sA1a:sA0a;
#pragma unroll
        for(int ks=0;ks<2;++ks){
            uint32_t a[L3][R2][4];
#pragma unroll
            for(int k=0;k<L3;++k)
#pragma unroll
                for(int r2=0;r2<R2;++r2)
                    LDSM4(a[k][r2], sAa+(k*1280+(rbase+r2*16)*20)*4+qb+ks*32);
#pragma unroll
            for(int k=0;k<L3;++k)
#pragma unroll
                for(int nc=0;nc<NC;++nc)
#pragma unroll
                    for(int r2=0;r2<R2;++r2)
                        mma16(acc[k][nc][r2],a[k][r2],breg[ks][nc]);
        }
        if(n+1<NCH){
            if((((n+1)*32)&(M2-1))==0) loadx1((n+1)*32/M2);
            compP(n+1);
        }
    }
}

template<int M3,int L3,int OFF3,int RG>
__device__ __forceinline__ void epilogue(float (&acc)[L3][M3*RG/64][4/RG][4],
    float* __restrict__ out,int tile,float coeff)
{
    constexpr int CGn=8/RG, CPW=M3/CGn, NC=CPW/8, R2=4/RG;
    const int tid=threadIdx.x, wid=tid>>5, lane=tid&31;
    const int cgp=wid/RG, rowg=wid%RG, gID=lane>>2, tIG=lane&3;
#pragma unroll
    for(int k=0;k<L3;++k)
#pragma unroll
        for(int nc=0;nc<NC;++nc)
#pragma unroll
            for(int r2=0;r2<R2;++r2){
                const int wc=cgp*CPW+nc*8+2*tIG;
                const int row=tile*64+rowg*(64/RG)+r2*16+gID;
                float* po=out+(size_t)row*480+OFF3;
                po[(wc+0)*L3+k]=coeff*acc[k][nc][r2][0];
                po[(wc+1)*L3+k]=coeff*acc[k][nc][r2][1];
                po+=8*480;
                po[(wc+0)*L3+k]=coeff*acc[k][nc][r2][2];
                po[(wc+1)*L3+k]=coeff*acc[k][nc][r2][3];
            }
}

__global__ void __launch_bounds__(NT,2)
tp_kernel(const float* __restrict__ x1,const float* __restrict__ x2,
          float* __restrict__ out,const __grid_constant__ TPParams P)
{
    extern __shared__ char sm[];
    float* scg=(float*)sm;
    for(int e=threadIdx.x;e<384;e+=NT) scg[e]=P.cg[e];
    const int tile=blockIdx.y;
    const float* X1=x1+(size_t)tile*64*480;
    const float* X2=x2+(size_t)tile*64*480;
    uint32_t* sx2h=(uint32_t*)(sm+OX2);

    if(blockIdx.x==0){
        uint32_t* T2=(uint32_t*)(sm+OAR);                  // 16384
        uint32_t* X1S=(uint32_t*)(sm+OAR+16384);           // 32768
        uint32_t* A0=(uint32_t*)(sm+OAR+49152);            // 5120
        uint32_t* A1=(uint32_t*)(sm+OAR+54272);
        uint32_t* W0=(uint32_t*)(sm+OAR+59392);            // 8192
        uint32_t* W1=(uint32_t*)(sm+OAR+67584);
        uint32_t a0=smem_u32(A0),a1=smem_u32(A1),w0=smem_u32(W0),w1=smem_u32(W1);
        float acc[1][4][2][4]={};
        path000(X1, X2, P.wpo[0], T2, X1S, W0, W1, w0, w1, acc);
        do_path<128,1,3,3, 64, 64,2>(X1+128,X2+128,P.wpo[4],scg+P.cgo[4],sx2h,A0,A1,a0,a1,W0,W1,w0,w1,acc);
        do_path<128,1,5,5, 32, 32,2>(X1+320,X2+320,P.wpo[9],scg+P.cgo[9],sx2h,A0,A1,a0,a1,W0,W1,w0,w1,acc);
        epilogue<128,1,0,2>(acc,out,tile,P.coeff[0]);
    } else if(blockIdx.x==1){
        uint32_t* A0=(uint32_t*)(sm+OAR);                  // 15360
        uint32_t* A1=(uint32_t*)(sm+OAR+15360);
        uint32_t* W0=(uint32_t*)(sm+OAR+30720);            // 4096
        uint32_t* W1=(uint32_t*)(sm+OAR+34816);
        uint32_t a0=smem_u32(A0),a1=smem_u32(A1),w0=smem_u32(W0),w1=smem_u32(W1);
        float acc[3][4][1][4]={};
        do_path<64,3,1,3,128, 64,4>(X1,    X2+128,P.wpo[1],scg+P.cgo[1],sx2h,A0,A1,a0,a1,W0,W1,w0,w1,acc);
        do_path<64,3,3,1, 64,128,4>(X1+128,X2,    P.wpo[3],scg+P.cgo[3],sx2h,A0,A1,a0,a1,W0,W1,w0,w1,acc);
        do_path<64,3,3,5, 64, 32,4>(X1+128,X2+320,P.wpo[6],scg+P.cgo[6],sx2h,A0,A1,a0,a1,W0,W1,w0,w1,acc);
        do_path<64,3,5,3, 32, 64,4>(X1+320,X2+128,P.wpo[8],scg+P.cgo[8],sx2h,A0,A1,a0,a1,W0,W1,w0,w1,acc);
        epilogue<64,3,128,4>(acc,out,tile,P.coeff[1]);
    } else {
        uint32_t* A0=(uint32_t*)(sm+OAR);                  // 25600
        uint32_t* A1=(uint32_t*)(sm+OAR+25600);
        uint32_t* W0=(uint32_t*)(sm+OAR+51200);            // 2048
        uint32_t* W1=(uint32_t*)(sm+OAR+53248);
        uint32_t a0=smem_u32(A0),a1=smem_u32(A1),w0=smem_u32(W0),w1=smem_u32(W1);
        float acc[5][2][1][4]={};
        do_path<32,5,1,5,128, 32,4>(X1,    X2+320,P.wpo[2], scg+P.cgo[2], sx2h,A0,A1,a0,a1,W0,W1,w0,w1,acc);
        do_path<32,5,3,3, 64, 64,4>(X1+128,X2+128,P.wpo[5], scg+P.cgo[5], sx2h,A0,A1,a0,a1,W0,W1,w0,w1,acc);
        do_path<32,5,5,1, 32,128,4>(X1+320,X2,    P.wpo[7], scg+P.cgo[7], sx2h,A0,A1,a0,a1,W0,W1,w0,w1,acc);
        do_path<32,5,5,5, 32, 32,4>(X1+320,X2+320,P.wpo[10],scg+P.cgo[10],sx2h,A0,A1,a0,a1,W0,W1,w0,w1,acc);
        epilogue<32,5,320,4>(acc,out,tile,P.coeff[2]);
    }
}

// ---------------------- host: CG construction (verified) --------------------

typedef std::complex<double> cpx;
static double fct(int n){double r=1.0;for(int i=2;i<=n;++i)r*=i;return r;}

static void change_basis(int l, cpx q[5][5]){
    for(int a=0;a<5;++a)for(int b=0;b<5;++b)q[a][b]=cpx(0,0);
    const double s2=1.0/std::sqrt(2.0);
    for(int m=-l;m<0;++m){ q[l+m][l-m]=cpx(s2,0); q[l+m][l+m]=cpx(0,-s2); }
    q[l][l]=cpx(1,0);
    for(int m=1;m<=l;++m){
        double sg=(m&1)?-1.0:1.0;
        q[l+m][l+m]=cpx(sg*s2,0); q[l+m][l-m]=cpx(0,sg*s2);
    }
    cpx ph(1,0);
    for(int t=0;t<l;++t)ph*=cpx(0,-1);
    for(int a=0;a<2*l+1;++a)for(int b=0;b<2*l+1;++b)q[a][b]*=ph;
}

static void real_cg(int l1,int l2,int l3,float outc[5][5][5]){
    cpx Q1[5][5],Q2[5][5],Q3[5][5];
    change_basis(l1,Q1); change_basis(l2,Q2); change_basis(l3,Q3);
    double C[5][5][5]; memset(C,0,sizeof(C));
    for(int m1=-l1;m1<=l1;++m1)
        for(int m2=-l2;m2<=l2;++m2){
            int m3=m1+m2;
            if(m3<-l3||m3>l3)continue;
            double pref=std::sqrt((2.0*l3+1.0)
                *fct(l3+l1-l2)*fct(l3-l1+l2)*fct(l1+l2-l3)/fct(l1+l2+l3+1)
                *fct(l3+m3)*fct(l3-m3)*fct(l1-m1)*fct(l1+m1)*fct(l2-m2)*fct(l2+m2));
            double s=0.0;
            for(int k=0;k<=l1+l2-l3;++k){
                if(l1-m1-k<0||l2+m2-k<0||l3-l2+m1+k<0||l3-l1-m2+k<0)continue;
                double d=fct(k)*fct(l1+l2-l3-k)*fct(l1-m1-k)
                        *fct(l2+m2-k)*fct(l3-l2+m1+k)*fct(l3-l1-m2+k);
                s+=((k&1)?-1.0:1.0)/d;
            }
            C[l1+m1][l2+m2][l3+m3]=pref*s;
        }
    int n1=2*l1+1,n2=2*l2+1,n3=2*l3+1;
    double Rr[5][5][5],nrm=0.0;
    for(int j=0;j<n1;++j)
        for(int lb=0;lb<n2;++lb)
            for(int nn=0;nn<n3;++nn){
                cpx a(0,0);
                for(int i=0;i<n1;++i)
                    for(int kk=0;kk<n2;++kk)
                        for(int m=0;m<n3;++m)
                            if(C[i][kk][m]!=0.0)
                                a+=Q1[i][j]*Q2[kk][lb]*Q3[m][nn]*C[i][kk][m];
                Rr[j][lb][nn]=a.real();
                nrm+=a.real()*a.real();
            }
    nrm=std::sqrt(nrm);
    for(int j=0;j<5;++j)for(int lb=0;lb<5;++lb)for(int nn=0;nn<5;++nn)
        outc[j][lb][nn]=(j<n1&&lb<n2&&nn<n3)?(float)(Rr[j][lb][nn]/nrm):0.f;
}

static void build_params(TPParams& P){
    memset(&P,0,sizeof(P));
    const int M_[3]={128,64,32}, L_[3]={0,1,2}, Pa[3]={1,-1,1};
    long long fan[3]={0,0,0};
    int woff=0, cgo=0, idx=0;
    for(int i1=0;i1<3;++i1)for(int i2=0;i2<3;++i2)for(int i3=0;i3<3;++i3){
        int l1=L_[i1],l2=L_[i2],l3=L_[i3];
        if(Pa[i1]*Pa[i2]!=Pa[i3])continue;
        if(l3<abs(l1-l2)||l3>l1+l2)continue;
        float C[5][5][5];
        real_cg(l1,l2,l3,C);
        P.woff[idx]=woff; P.cgo[idx]=cgo;
        P.wpo[idx]=woff/2; P.m3s[idx]=M_[i3];
        int n1=2*l1+1,n2=2*l2+1,n3=2*l3+1;
        for(int i=0;i<n1;++i)for(int j=0;j<n2;++j)for(int k=0;k<n3;++k)
            P.cg[cgo++]=C[i][j][k];
        woff+=M_[i1]*M_[i2]*M_[i3];
        fan[i3]+=(long long)M_[i1]*M_[i2];
        ++idx;
    }
    P.wpo[11]=woff/2;
    for(int t=0;t<3;++t)
        P.coeff[t]=(float)std::sqrt((double)(2*L_[t]+1)/(double)fan[t]);
}

// ------------------------------ entry ---------------------------------------

extern "C" void kernel_launch(void* const* d_in, const int* in_sizes, int n_in,
                              void* d_out, int out_size) {
    TPParams P;
    build_params(P);
    wpre_kernel<<<(P.wpo[11]+255)/256, 256>>>((const float*)d_in[2], P);
    cudaFuncSetAttribute(tp_kernel, cudaFuncAttributeMaxDynamicSharedMemorySize, SMT);
    tp_kernel<<<dim3(3,128), NT, SMT>>>(
        (const float*)d_in[0], (const float*)d_in[1], (float*)d_out, P);
}

// round 14
// speedup vs baseline: 1.5411x; 1.0612x over previous
#include <cuda_runtime.h>
#include <cuda_fp16.h>
#include <cstdint>
#include <cmath>
#include <cstring>
#include <complex>
#include <cstdlib>

#define NT 256
struct TPParams {
    float cg[384]; float coeff[3];
    int cgo[12], woff[12], wpo[12], m3s[12];
};

__device__ uint32_t g_wp[2244608];   // W half2, [path][chunk'][w][perm(kpair)]

// smem: cg[0:1536) | sx2h[1536:26880) | variant arena from 26880
#define OX2 1536
#define OAR 26880
#define SMT 86272

__device__ __forceinline__ uint32_t pack2(float lo, float hi){
    uint32_t r; asm("cvt.rn.f16x2.f32 %0,%1,%2;":"=r"(r):"f"(hi),"f"(lo)); return r;
}
__device__ __forceinline__ uint32_t hmul2u(uint32_t a, uint32_t b){
    uint32_t r; asm("mul.rn.f16x2 %0,%1,%2;":"=r"(r):"r"(a),"r"(b)); return r;
}
__device__ __forceinline__ uint32_t smem_u32(const void* p){
    uint32_t a;
    asm("{ .reg .u64 t; cvta.to.shared.u64 t, %1; cvt.u32.u64 %0, t; }":"=r"(a):"l"(p));
    return a;
}
__device__ __forceinline__ void mma16(float* d,const uint32_t* a,const uint32_t* b){
    asm volatile("mma.sync.aligned.m16n8k16.row.col.f32.f16.f16.f32 "
        "{%0,%1,%2,%3},{%4,%5,%6,%7},{%8,%9},{%0,%1,%2,%3};"
        :"+f"(d[0]),"+f"(d[1]),"+f"(d[2]),"+f"(d[3])
        :"r"(a[0]),"r"(a[1]),"r"(a[2]),"r"(a[3]),"r"(b[0]),"r"(b[1]));
}
#define LDSM4(r,addr) asm volatile( \
    "ldmatrix.sync.aligned.m8n8.x4.shared.b16 {%0,%1,%2,%3},[%4];" \
    :"=r"((r)[0]),"=r"((r)[1]),"=r"((r)[2]),"=r"((r)[3]):"r"(addr))

// ---- W prepass: pos=perm(p); path 0 additionally cgr-major chunk order -----
__global__ void wpre_kernel(const float* __restrict__ w,
                            const __grid_constant__ TPParams P){
    int r = blockIdx.x*256 + threadIdx.x;
    if(r >= P.wpo[11]) return;
    int t = 0;
    while(r >= P.wpo[t+1]) ++t;
    int loc = r - P.wpo[t], M3 = P.m3s[t];
    int n = loc/(16*M3), rem = loc - n*16*M3, w_ = rem>>4, pos = rem&15;
    int p = ((pos&3)<<2) + (pos>>2);
    int nl = (t==0) ? ((n&127)*4 + (n>>7)) : n;   // storage n' -> logical n
    const float* s = w + P.woff[t] + (size_t)(nl*32 + 2*p)*M3 + w_;
    g_wp[r] = pack2(s[0], s[M3]);
}

// ---- specialized path (1,1,1): barrier-free mainloop, B direct LDG ---------
__device__ __forceinline__ void path000(
    const float* __restrict__ gx1, const float* __restrict__ gx2, int wpo,
    uint32_t* sx2t, uint32_t* x1s,
    float (&acc)[1][4][2][4])
{
    const int tid=threadIdx.x, wid=tid>>5, lane=tid&31;
    const int cgp=wid>>1, rowg=wid&1, gID=lane>>2, tIG=lane&3;
    __syncthreads();
    // stage x2 tile [cgr][b][perm(vpair)] as half2
    for(int idx=tid; idx<4096; idx+=NT){
        int cgr=idx>>10, rem=idx&1023, b=rem>>4, pos=rem&15;
        int p=((pos&3)<<2)+(pos>>2), v=cgr*32+2*p;
        sx2t[idx]=pack2(gx2[b*480+v], gx2[b*480+v+1]);
    }
    // stage x1 as duplicated half2: x1s[u*64+row]
    for(int idx=tid; idx<8192; idx+=NT){
        int u=idx>>6, row=idx&63;
        float v=gx1[row*480+u];
        x1s[idx]=pack2(v,v);
    }
    __syncthreads();

    const uint4* gB=(const uint4*)(g_wp+wpo)+(cgp*32+gID)*4+tIG;
    uint4 bv[4];
    auto ldB=[&](int n){
        const uint4* g=gB+(size_t)n*512;
        bv[0]=g[0]; bv[1]=g[32]; bv[2]=g[64]; bv[3]=g[96];
    };
    ldB(0);
#pragma unroll 1
    for(int cgr=0;cgr<4;++cgr){
        uint4 xv0[2], xv1[2];
#pragma unroll
        for(int r2=0;r2<2;++r2){
            const uint32_t* base=sx2t+cgr*1024+(rowg*32+r2*16+gID)*16+tIG*4;
            xv0[r2]=*(const uint4*)base;
            xv1[r2]=*(const uint4*)(base+128);
        }
#pragma unroll 1
        for(int u=0;u<128;++u){
            const int n=cgr*128+u;
            uint4 cur[4];
#pragma unroll
            for(int nc=0;nc<4;++nc) cur[nc]=bv[nc];
            if(n+1<512) ldB(n+1);           // prefetch next chunk
            uint32_t x1h[2][2];
#pragma unroll
            for(int r2=0;r2<2;++r2)
#pragma unroll
                for(int h=0;h<2;++h)
                    x1h[r2][h]=x1s[u*64+rowg*32+r2*16+gID+h*8];
#pragma unroll
            for(int ks=0;ks<2;++ks){
                uint32_t a[2][4];
#pragma unroll
                for(int r2=0;r2<2;++r2){
                    uint32_t s0=ks?xv0[r2].z:xv0[r2].x, s1=ks?xv1[r2].z:xv1[r2].x;
                    uint32_t s2=ks?xv0[r2].w:xv0[r2].y, s3=ks?xv1[r2].w:xv1[r2].y;
                    a[r2][0]=hmul2u(s0,x1h[r2][0]); a[r2][1]=hmul2u(s1,x1h[r2][1]);
                    a[r2][2]=hmul2u(s2,x1h[r2][0]); a[r2][3]=hmul2u(s3,x1h[r2][1]);
                }
#pragma unroll
                for(int nc=0;nc<4;++nc){
                    uint32_t bb[2];
                    bb[0]=ks?cur[nc].z:cur[nc].x;
                    bb[1]=ks?cur[nc].w:cur[nc].y;
#pragma unroll
                    for(int r2=0;r2<2;++r2)
                        mma16(acc[0][nc][r2],a[r2],bb);
                }
            }
        }
    }
}

// ---- generic fused path: B direct LDG, sA double-buffered ------------------
template<int M3,int L3,int L1,int L2,int M1,int M2,int RG>
__device__ __forceinline__ void do_path(
    const float* __restrict__ gx1, const float* __restrict__ gx2,
    int wpo, const float* __restrict__ cg,
    uint32_t* sx2h, uint32_t* sA0, uint32_t* sA1, uint32_t sA0a, uint32_t sA1a,
    float (&acc)[L3][M3*RG/64][4/RG][4])
{
    constexpr int CGn=8/RG, CPW=M3/CGn, NC=CPW/8, R2=4/RG;
    constexpr int NCH=M1*M2/32, C=(M2/2)*L2;
    const int tid=threadIdx.x, wid=tid>>5, lane=tid&31;
    const int cgp=wid/RG, rowg=wid%RG, gID=lane>>2, tIG=lane&3;
    const int q=tid&15, bg=tid>>4;
    const int rbase=rowg*(64/RG)+(lane&7)+((lane>>3)&1)*8;
    const int qb=((lane>>4)&1)*16;

    __syncthreads();
    for(int idx=tid; idx<64*C; idx+=NT){
        int b=idx/C, c=idx-b*C, vp=c/L2, j=c-vp*L2;
        float lo=gx2[b*480+(2*vp)*L2+j], hi=gx2[b*480+(2*vp+1)*L2+j];
        sx2h[c*66+b]=pack2(lo,hi);
    }
    __syncthreads();

    float rx1[4][L1];
    auto loadx1=[&](int u){
#pragma unroll
        for(int it=0;it<4;++it)
#pragma unroll
            for(int i=0;i<L1;++i)
                rx1[it][i]=gx1[(it*16+bg)*480+u*L1+i];
    };
    const uint4* gB=(const uint4*)(g_wp+wpo)+(cgp*CPW+gID)*4+tIG;
    uint4 bv[NC];
    auto ldB=[&](int n){
        const uint4* g=gB+(size_t)n*(4*M3);
#pragma unroll
        for(int nc=0;nc<NC;++nc) bv[nc]=g[nc*32];
    };
    auto compP=[&](int n){
        uint32_t* d=(n&1)?sA1:sA0;
        const int vp0=((n*32)&(M2-1))>>1;
        const uint32_t* c2=sx2h+(vp0+q)*L2*66;
#pragma unroll
        for(int it=0;it<4;++it){
            const int b=it*16+bg;
            float2 cf[L2];
#pragma unroll
            for(int j=0;j<L2;++j){
                uint32_t cw=c2[j*66+b];
                cf[j]=__half22float2(*(__half2*)&cw);
            }
            float pa[L3], pb[L3];
#pragma unroll
            for(int k=0;k<L3;++k){ pa[k]=0.f; pb[k]=0.f; }
#pragma unroll
            for(int i=0;i<L1;++i){
                const float xi=rx1[it][i];
#pragma unroll
                for(int j=0;j<L2;++j){
                    float xa=xi*cf[j].x, xb=xi*cf[j].y;
#pragma unroll
                    for(int k=0;k<L3;++k){
                        float cc=cg[(i*L2+j)*L3+k];
                        pa[k]+=cc*xa; pb[k]+=cc*xb;
                    }
                }
            }
#pragma unroll
            for(int k=0;k<L3;++k) d[k*1280+b*20+q]=pack2(pa[k],pb[k]);
        }
    };

    loadx1(0); compP(0); ldB(0);
#pragma unroll 1
    for(int n=0;n<NCH;++n){
        __syncthreads();             // sA(n) ready; prev MMA done
        const uint32_t sAa=(n&1)?sA1a:sA0a;
        uint32_t breg[2][NC][2];
#pragma unroll
        for(int nc=0;nc<NC;++nc){
            breg[0][nc][0]=bv[nc].x; breg[0][nc][1]=bv[nc].y;
            breg[1][nc][0]=bv[nc].z; breg[1][nc][1]=bv[nc].w;
        }
#pragma unroll
        for(int ks=0;ks<2;++ks){
            uint32_t a[L3][R2][4];
#pragma unroll
            for(int k=0;k<L3;++k)
#pragma unroll
                for(int r2=0;r2<R2;++r2)
                    LDSM4(a[k][r2], sAa+(k*1280+(rbase+r2*16)*20)*4+qb+ks*32);
#pragma unroll
            for(int k=0;k<L3;++k)
#pragma unroll
                for(int nc=0;nc<NC;++nc)
#pragma unroll
                    for(int r2=0;r2<R2;++r2)
                        mma16(acc[k][nc][r2],a[k][r2],breg[ks][nc]);
        }
        if(n+1<NCH){
            ldB(n+1);                // prefetch: consumed after next barrier
            if((((n+1)*32)&(M2-1))==0) loadx1((n+1)*32/M2);
            compP(n+1);
        }
    }
}

template<int M3,int L3,int OFF3,int RG>
__device__ __forceinline__ void epilogue(float (&acc)[L3][M3*RG/64][4/RG][4],
    float* __restrict__ out,int tile,float coeff)
{
    constexpr int CGn=8/RG, CPW=M3/CGn, NC=CPW/8, R2=4/RG;
    const int tid=threadIdx.x, wid=tid>>5, lane=tid&31;
    const int cgp=wid/RG, rowg=wid%RG, gID=lane>>2, tIG=lane&3;
#pragma unroll
    for(int k=0;k<L3;++k)
#pragma unroll
        for(int nc=0;nc<NC;++nc)
#pragma unroll
            for(int r2=0;r2<R2;++r2){
                const int wc=cgp*CPW+nc*8+2*tIG;
                const int row=tile*64+rowg*(64/RG)+r2*16+gID;
                float* po=out+(size_t)row*480+OFF3;
                po[(wc+0)*L3+k]=coeff*acc[k][nc][r2][0];
                po[(wc+1)*L3+k]=coeff*acc[k][nc][r2][1];
                po+=8*480;
                po[(wc+0)*L3+k]=coeff*acc[k][nc][r2][2];
                po[(wc+1)*L3+k]=coeff*acc[k][nc][r2][3];
            }
}

__global__ void __launch_bounds__(NT,2)
tp_kernel(const float* __restrict__ x1,const float* __restrict__ x2,
          float* __restrict__ out,const __grid_constant__ TPParams P)
{
    extern __shared__ char sm[];
    float* scg=(float*)sm;
    for(int e=threadIdx.x;e<384;e+=NT) scg[e]=P.cg[e];
    const int tile=blockIdx.y;
    const float* X1=x1+(size_t)tile*64*480;
    const float* X2=x2+(size_t)tile*64*480;
    uint32_t* sx2h=(uint32_t*)(sm+OX2);

    if(blockIdx.x==0){
        uint32_t* T2=(uint32_t*)(sm+OAR);                  // 16384
        uint32_t* X1S=(uint32_t*)(sm+OAR+16384);           // 32768
        uint32_t* A0=(uint32_t*)(sm+OAR+49152);            // 5120
        uint32_t* A1=(uint32_t*)(sm+OAR+54272);
        uint32_t a0=smem_u32(A0),a1=smem_u32(A1);
        float acc[1][4][2][4]={};
        path000(X1, X2, P.wpo[0], T2, X1S, acc);
        do_path<128,1,3,3, 64, 64,2>(X1+128,X2+128,P.wpo[4],scg+P.cgo[4],sx2h,A0,A1,a0,a1,acc);
        do_path<128,1,5,5, 32, 32,2>(X1+320,X2+320,P.wpo[9],scg+P.cgo[9],sx2h,A0,A1,a0,a1,acc);
        epilogue<128,1,0,2>(acc,out,tile,P.coeff[0]);
    } else if(blockIdx.x==1){
        uint32_t* A0=(uint32_t*)(sm+OAR);                  // 15360
        uint32_t* A1=(uint32_t*)(sm+OAR+15360);
        uint32_t a0=smem_u32(A0),a1=smem_u32(A1);
        float acc[3][4][1][4]={};
        do_path<64,3,1,3,128, 64,4>(X1,    X2+128,P.wpo[1],scg+P.cgo[1],sx2h,A0,A1,a0,a1,acc);
        do_path<64,3,3,1, 64,128,4>(X1+128,X2,    P.wpo[3],scg+P.cgo[3],sx2h,A0,A1,a0,a1,acc);
        do_path<64,3,3,5, 64, 32,4>(X1+128,X2+320,P.wpo[6],scg+P.cgo[6],sx2h,A0,A1,a0,a1,acc);
        do_path<64,3,5,3, 32, 64,4>(X1+320,X2+128,P.wpo[8],scg+P.cgo[8],sx2h,A0,A1,a0,a1,acc);
        epilogue<64,3,128,4>(acc,out,tile,P.coeff[1]);
    } else {
        uint32_t* A0=(uint32_t*)(sm+OAR);                  // 25600
        uint32_t* A1=(uint32_t*)(sm+OAR+25600);
        uint32_t a0=smem_u32(A0),a1=smem_u32(A1);
        float acc[5][2][1][4]={};
        do_path<32,5,1,5,128, 32,4>(X1,    X2+320,P.wpo[2], scg+P.cgo[2], sx2h,A0,A1,a0,a1,acc);
        do_path<32,5,3,3, 64, 64,4>(X1+128,X2+128,P.wpo[5], scg+P.cgo[5], sx2h,A0,A1,a0,a1,acc);
        do_path<32,5,5,1, 32,128,4>(X1+320,X2,    P.wpo[7], scg+P.cgo[7], sx2h,A0,A1,a0,a1,acc);
        do_path<32,5,5,5, 32, 32,4>(X1+320,X2+320,P.wpo[10],scg+P.cgo[10],sx2h,A0,A1,a0,a1,acc);
        epilogue<32,5,320,4>(acc,out,tile,P.coeff[2]);
    }
}

// ---------------------- host: CG construction (verified) --------------------

typedef std::complex<double> cpx;
static double fct(int n){double r=1.0;for(int i=2;i<=n;++i)r*=i;return r;}

static void change_basis(int l, cpx q[5][5]){
    for(int a=0;a<5;++a)for(int b=0;b<5;++b)q[a][b]=cpx(0,0);
    const double s2=1.0/std::sqrt(2.0);
    for(int m=-l;m<0;++m){ q[l+m][l-m]=cpx(s2,0); q[l+m][l+m]=cpx(0,-s2); }
    q[l][l]=cpx(1,0);
    for(int m=1;m<=l;++m){
        double sg=(m&1)?-1.0:1.0;
        q[l+m][l+m]=cpx(sg*s2,0); q[l+m][l-m]=cpx(0,sg*s2);
    }
    cpx ph(1,0);
    for(int t=0;t<l;++t)ph*=cpx(0,-1);
    for(int a=0;a<2*l+1;++a)for(int b=0;b<2*l+1;++b)q[a][b]*=ph;
}

static void real_cg(int l1,int l2,int l3,float outc[5][5][5]){
    cpx Q1[5][5],Q2[5][5],Q3[5][5];
    change_basis(l1,Q1); change_basis(l2,Q2); change_basis(l3,Q3);
    double C[5][5][5]; memset(C,0,sizeof(C));
    for(int m1=-l1;m1<=l1;++m1)
        for(int m2=-l2;m2<=l2;++m2){
            int m3=m1+m2;
            if(m3<-l3||m3>l3)continue;
            double pref=std::sqrt((2.0*l3+1.0)
                *fct(l3+l1-l2)*fct(l3-l1+l2)*fct(l1+l2-l3)/fct(l1+l2+l3+1)
                *fct(l3+m3)*fct(l3-m3)*fct(l1-m1)*fct(l1+m1)*fct(l2-m2)*fct(l2+m2));
            double s=0.0;
            for(int k=0;k<=l1+l2-l3;++k){
                if(l1-m1-k<0||l2+m2-k<0||l3-l2+m1+k<0||l3-l1-m2+k<0)continue;
                double d=fct(k)*fct(l1+l2-l3-k)*fct(l1-m1-k)
                        *fct(l2+m2-k)*fct(l3-l2+m1+k)*fct(l3-l1-m2+k);
                s+=((k&1)?-1.0:1.0)/d;
            }
            C[l1+m1][l2+m2][l3+m3]=pref*s;
        }
    int n1=2*l1+1,n2=2*l2+1,n3=2*l3+1;
    double Rr[5][5][5],nrm=0.0;
    for(int j=0;j<n1;++j)
        for(int lb=0;lb<n2;++lb)
            for(int nn=0;nn<n3;++nn){
                cpx a(0,0);
                for(int i=0;i<n1;++i)
                    for(int kk=0;kk<n2;++kk)
                        for(int m=0;m<n3;++m)
                            if(C[i][kk][m]!=0.0)
                                a+=Q1[i][j]*Q2[kk][lb]*Q3[m][nn]*C[i][kk][m];
                Rr[j][lb][nn]=a.real();
                nrm+=a.real()*a.real();
            }
    nrm=std::sqrt(nrm);
    for(int j=0;j<5;++j)for(int lb=0;lb<5;++lb)for(int nn=0;nn<5;++nn)
        outc[j][lb][nn]=(j<n1&&lb<n2&&nn<n3)?(float)(Rr[j][lb][nn]/nrm):0.f;
}

static void build_params(TPParams& P){
    memset(&P,0,sizeof(P));
    const int M_[3]={128,64,32}, L_[3]={0,1,2}, Pa[3]={1,-1,1};
    long long fan[3]={0,0,0};
    int woff=0, cgo=0, idx=0;
    for(int i1=0;i1<3;++i1)for(int i2=0;i2<3;++i2)for(int i3=0;i3<3;++i3){
        int l1=L_[i1],l2=L_[i2],l3=L_[i3];
        if(Pa[i1]*Pa[i2]!=Pa[i3])continue;
        if(l3<abs(l1-l2)||l3>l1+l2)continue;
        float C[5][5][5];
        real_cg(l1,l2,l3,C);
        P.woff[idx]=woff; P.cgo[idx]=cgo;
        P.wpo[idx]=woff/2; P.m3s[idx]=M_[i3];
        int n1=2*l1+1,n2=2*l2+1,n3=2*l3+1;
        for(int i=0;i<n1;++i)for(int j=0;j<n2;++j)for(int k=0;k<n3;++k)
            P.cg[cgo++]=C[i][j][k];
        woff+=M_[i1]*M_[i2]*M_[i3];
        fan[i3]+=(long long)M_[i1]*M_[i2];
        ++idx;
    }
    P.wpo[11]=woff/2;
    for(int t=0;t<3;++t)
        P.coeff[t]=(float)std::sqrt((double)(2*L_[t]+1)/(double)fan[t]);
}

// ------------------------------ entry ---------------------------------------

extern "C" void kernel_launch(void* const* d_in, const int* in_sizes, int n_in,
                              void* d_out, int out_size) {
    TPParams P;
    build_params(P);
    wpre_kernel<<<(P.wpo[11]+255)/256, 256>>>((const float*)d_in[2], P);
    cudaFuncSetAttribute(tp_kernel, cudaFuncAttributeMaxDynamicSharedMemorySize, SMT);
    tp_kernel<<<dim3(3,128), NT, SMT>>>(
        (const float*)d_in[0], (const float*)d_in[1], (float*)d_out, P);
}

// round 15
// speedup vs baseline: 1.9771x; 1.2829x over previous
#include <cuda_runtime.h>
#include <cuda_fp16.h>
#include <cstdint>
#include <cmath>
#include <cstring>
#include <complex>
#include <cstdlib>

#define NT 256
struct TPParams {
    float cg[384]; float coeff[3];
    int cgo[12], woff[12], wpo[12], m3s[12];
};

__device__ uint32_t g_wp[2244608];   // W half2, [path][chunk'][w][perm(kpair)]

// smem: cg[0:1536) | sx2h[1536:26880) | variant arena from 26880
#define OX2 1536
#define OAR 26880
#define SMT 86272

// compile-time CG support superset: c in {a+b, |a-b|}  (phi-frequency rule)
__device__ __host__ constexpr bool cg_nz(int L1,int L2,int L3,int i,int j,int k){
    int l1=(L1-1)/2, l2=(L2-1)/2, l3=(L3-1)/2;
    int a=i-l1; a=a<0?-a:a;
    int b=j-l2; b=b<0?-b:b;
    int c=k-l3; c=c<0?-c:c;
    int d=a-b; d=d<0?-d:d;
    return (c==a+b)||(c==d);
}

__device__ __forceinline__ uint32_t pack2(float lo, float hi){
    uint32_t r; asm("cvt.rn.f16x2.f32 %0,%1,%2;":"=r"(r):"f"(hi),"f"(lo)); return r;
}
__device__ __forceinline__ uint32_t hmul2u(uint32_t a, uint32_t b){
    uint32_t r; asm("mul.rn.f16x2 %0,%1,%2;":"=r"(r):"r"(a),"r"(b)); return r;
}
__device__ __forceinline__ uint32_t smem_u32(const void* p){
    uint32_t a;
    asm("{ .reg .u64 t; cvta.to.shared.u64 t, %1; cvt.u32.u64 %0, t; }":"=r"(a):"l"(p));
    return a;
}
__device__ __forceinline__ void mma16(float* d,const uint32_t* a,const uint32_t* b){
    asm volatile("mma.sync.aligned.m16n8k16.row.col.f32.f16.f16.f32 "
        "{%0,%1,%2,%3},{%4,%5,%6,%7},{%8,%9},{%0,%1,%2,%3};"
        :"+f"(d[0]),"+f"(d[1]),"+f"(d[2]),"+f"(d[3])
        :"r"(a[0]),"r"(a[1]),"r"(a[2]),"r"(a[3]),"r"(b[0]),"r"(b[1]));
}
#define LDSM4(r,addr) asm volatile( \
    "ldmatrix.sync.aligned.m8n8.x4.shared.b16 {%0,%1,%2,%3},[%4];" \
    :"=r"((r)[0]),"=r"((r)[1]),"=r"((r)[2]),"=r"((r)[3]):"r"(addr))

// ---- W prepass: pos=perm(p); path 0 additionally cgr-major chunk order -----
__global__ void wpre_kernel(const float* __restrict__ w,
                            const __grid_constant__ TPParams P){
    int r = blockIdx.x*256 + threadIdx.x;
    if(r >= P.wpo[11]) return;
    int t = 0;
    while(r >= P.wpo[t+1]) ++t;
    int loc = r - P.wpo[t], M3 = P.m3s[t];
    int n = loc/(16*M3), rem = loc - n*16*M3, w_ = rem>>4, pos = rem&15;
    int p = ((pos&3)<<2) + (pos>>2);
    int nl = (t==0) ? ((n&127)*4 + (n>>7)) : n;   // storage n' -> logical n
    const float* s = w + P.woff[t] + (size_t)(nl*32 + 2*p)*M3 + w_;
    g_wp[r] = pack2(s[0], s[M3]);
}

// ---- specialized path (1,1,1): barrier-free mainloop, B direct LDG ---------
__device__ __forceinline__ void path000(
    const float* __restrict__ gx1, const float* __restrict__ gx2, int wpo,
    uint32_t* sx2t, uint32_t* x1s,
    float (&acc)[1][4][2][4])
{
    const int tid=threadIdx.x, wid=tid>>5, lane=tid&31;
    const int cgp=wid>>1, rowg=wid&1, gID=lane>>2, tIG=lane&3;
    __syncthreads();
    for(int idx=tid; idx<4096; idx+=NT){
        int cgr=idx>>10, rem=idx&1023, b=rem>>4, pos=rem&15;
        int p=((pos&3)<<2)+(pos>>2), v=cgr*32+2*p;
        sx2t[idx]=pack2(gx2[b*480+v], gx2[b*480+v+1]);
    }
    for(int idx=tid; idx<8192; idx+=NT){
        int u=idx>>6, row=idx&63;
        float v=gx1[row*480+u];
        x1s[idx]=pack2(v,v);
    }
    __syncthreads();

    const uint4* gB=(const uint4*)(g_wp+wpo)+(cgp*32+gID)*4+tIG;
    uint4 bv[4];
    auto ldB=[&](int n){
        const uint4* g=gB+(size_t)n*512;
        bv[0]=g[0]; bv[1]=g[32]; bv[2]=g[64]; bv[3]=g[96];
    };
    ldB(0);
#pragma unroll 1
    for(int cgr=0;cgr<4;++cgr){
        uint4 xv0[2], xv1[2];
#pragma unroll
        for(int r2=0;r2<2;++r2){
            const uint32_t* base=sx2t+cgr*1024+(rowg*32+r2*16+gID)*16+tIG*4;
            xv0[r2]=*(const uint4*)base;
            xv1[r2]=*(const uint4*)(base+128);
        }
#pragma unroll 1
        for(int u=0;u<128;++u){
            const int n=cgr*128+u;
            uint4 cur[4];
#pragma unroll
            for(int nc=0;nc<4;++nc) cur[nc]=bv[nc];
            if(n+1<512) ldB(n+1);
            uint32_t x1h[2][2];
#pragma unroll
            for(int r2=0;r2<2;++r2)
#pragma unroll
                for(int h=0;h<2;++h)
                    x1h[r2][h]=x1s[u*64+rowg*32+r2*16+gID+h*8];
#pragma unroll
            for(int ks=0;ks<2;++ks){
                uint32_t a[2][4];
#pragma unroll
                for(int r2=0;r2<2;++r2){
                    uint32_t s0=ks?xv0[r2].z:xv0[r2].x, s1=ks?xv1[r2].z:xv1[r2].x;
                    uint32_t s2=ks?xv0[r2].w:xv0[r2].y, s3=ks?xv1[r2].w:xv1[r2].y;
                    a[r2][0]=hmul2u(s0,x1h[r2][0]); a[r2][1]=hmul2u(s1,x1h[r2][1]);
                    a[r2][2]=hmul2u(s2,x1h[r2][0]); a[r2][3]=hmul2u(s3,x1h[r2][1]);
                }
#pragma unroll
                for(int nc=0;nc<4;++nc){
                    uint32_t bb[2];
                    bb[0]=ks?cur[nc].z:cur[nc].x;
                    bb[1]=ks?cur[nc].w:cur[nc].y;
#pragma unroll
                    for(int r2=0;r2<2;++r2)
                        mma16(acc[0][nc][r2],a[r2],bb);
                }
            }
        }
    }
}

// ---- generic fused path: sparse-masked compP, B direct LDG -----------------
template<int M3,int L3,int L1,int L2,int M1,int M2,int RG>
__device__ __forceinline__ void do_path(
    const float* __restrict__ gx1, const float* __restrict__ gx2,
    int wpo, const float* __restrict__ cg,
    uint32_t* sx2h, uint32_t* sA0, uint32_t* sA1, uint32_t sA0a, uint32_t sA1a,
    float (&acc)[L3][M3*RG/64][4/RG][4])
{
    constexpr int CGn=8/RG, CPW=M3/CGn, NC=CPW/8, R2=4/RG;
    constexpr int NCH=M1*M2/32, C=(M2/2)*L2;
    const int tid=threadIdx.x, wid=tid>>5, lane=tid&31;
    const int cgp=wid/RG, rowg=wid%RG, gID=lane>>2, tIG=lane&3;
    const int q=tid&15, bg=tid>>4;
    const int rbase=rowg*(64/RG)+(lane&7)+((lane>>3)&1)*8;
    const int qb=((lane>>4)&1)*16;

    __syncthreads();
    for(int idx=tid; idx<64*C; idx+=NT){
        int b=idx/C, c=idx-b*C, vp=c/L2, j=c-vp*L2;
        float lo=gx2[b*480+(2*vp)*L2+j], hi=gx2[b*480+(2*vp+1)*L2+j];
        sx2h[c*66+b]=pack2(lo,hi);
    }
    __syncthreads();

    float rx1[4][L1];
    auto loadx1=[&](int u){
#pragma unroll
        for(int it=0;it<4;++it)
#pragma unroll
            for(int i=0;i<L1;++i)
                rx1[it][i]=gx1[(it*16+bg)*480+u*L1+i];
    };
    const uint4* gB=(const uint4*)(g_wp+wpo)+(cgp*CPW+gID)*4+tIG;
    uint4 bv[NC];
    auto ldB=[&](int n){
        const uint4* g=gB+(size_t)n*(4*M3);
#pragma unroll
        for(int nc=0;nc<NC;++nc) bv[nc]=g[nc*32];
    };
    auto compP=[&](int n){
        uint32_t* d=(n&1)?sA1:sA0;
        const int vp0=((n*32)&(M2-1))>>1;
        const uint32_t* c2=sx2h+(vp0+q)*L2*66;
#pragma unroll
        for(int it=0;it<4;++it){
            const int b=it*16+bg;
            float2 cf[L2];
#pragma unroll
            for(int j=0;j<L2;++j){
                uint32_t cw=c2[j*66+b];
                cf[j]=__half22float2(*(__half2*)&cw);
            }
            float pa[L3], pb[L3];
#pragma unroll
            for(int k=0;k<L3;++k){ pa[k]=0.f; pb[k]=0.f; }
#pragma unroll
            for(int i=0;i<L1;++i){
                const float xi=rx1[it][i];
#pragma unroll
                for(int j=0;j<L2;++j){
                    float xa=xi*cf[j].x, xb=xi*cf[j].y;
#pragma unroll
                    for(int k=0;k<L3;++k){
                        if(cg_nz(L1,L2,L3,i,j,k)){   // compile-time folded
                            float cc=cg[(i*L2+j)*L3+k];
                            pa[k]+=cc*xa; pb[k]+=cc*xb;
                        }
                    }
                }
            }
#pragma unroll
            for(int k=0;k<L3;++k) d[k*1280+b*20+q]=pack2(pa[k],pb[k]);
        }
    };

    loadx1(0); compP(0); ldB(0);
#pragma unroll 1
    for(int n=0;n<NCH;++n){
        __syncthreads();             // sA(n) ready; prev MMA done
        const uint32_t sAa=(n&1)?sA1a:sA0a;
        uint32_t breg[2][NC][2];
#pragma unroll
        for(int nc=0;nc<NC;++nc){
            breg[0][nc][0]=bv[nc].x; breg[0][nc][1]=bv[nc].y;
            breg[1][nc][0]=bv[nc].z; breg[1][nc][1]=bv[nc].w;
        }
#pragma unroll
        for(int ks=0;ks<2;++ks){
            uint32_t a[L3][R2][4];
#pragma unroll
            for(int k=0;k<L3;++k)
#pragma unroll
                for(int r2=0;r2<R2;++r2)
                    LDSM4(a[k][r2], sAa+(k*1280+(rbase+r2*16)*20)*4+qb+ks*32);
#pragma unroll
            for(int k=0;k<L3;++k)
#pragma unroll
                for(int nc=0;nc<NC;++nc)
#pragma unroll
                    for(int r2=0;r2<R2;++r2)
                        mma16(acc[k][nc][r2],a[k][r2],breg[ks][nc]);
        }
        if(n+1<NCH){
            ldB(n+1);
            if((((n+1)*32)&(M2-1))==0) loadx1((n+1)*32/M2);
            compP(n+1);
        }
    }
}

template<int M3,int L3,int OFF3,int RG>
__device__ __forceinline__ void epilogue(float (&acc)[L3][M3*RG/64][4/RG][4],
    float* __restrict__ out,int tile,float coeff)
{
    constexpr int CGn=8/RG, CPW=M3/CGn, NC=CPW/8, R2=4/RG;
    const int tid=threadIdx.x, wid=tid>>5, lane=tid&31;
    const int cgp=wid/RG, rowg=wid%RG, gID=lane>>2, tIG=lane&3;
#pragma unroll
    for(int k=0;k<L3;++k)
#pragma unroll
        for(int nc=0;nc<NC;++nc)
#pragma unroll
            for(int r2=0;r2<R2;++r2){
                const int wc=cgp*CPW+nc*8+2*tIG;
                const int row=tile*64+rowg*(64/RG)+r2*16+gID;
                float* po=out+(size_t)row*480+OFF3;
                po[(wc+0)*L3+k]=coeff*acc[k][nc][r2][0];
                po[(wc+1)*L3+k]=coeff*acc[k][nc][r2][1];
                po+=8*480;
                po[(wc+0)*L3+k]=coeff*acc[k][nc][r2][2];
                po[(wc+1)*L3+k]=coeff*acc[k][nc][r2][3];
            }
}

__global__ void __launch_bounds__(NT,2)
tp_kernel(const float* __restrict__ x1,const float* __restrict__ x2,
          float* __restrict__ out,const __grid_constant__ TPParams P)
{
    extern __shared__ char sm[];
    float* scg=(float*)sm;
    for(int e=threadIdx.x;e<384;e+=NT) scg[e]=P.cg[e];
    const int tile=blockIdx.y;
    const float* X1=x1+(size_t)tile*64*480;
    const float* X2=x2+(size_t)tile*64*480;
    uint32_t* sx2h=(uint32_t*)(sm+OX2);

    if(blockIdx.x==0){
        uint32_t* T2=(uint32_t*)(sm+OAR);                  // 16384
        uint32_t* X1S=(uint32_t*)(sm+OAR+16384);           // 32768
        uint32_t* A0=(uint32_t*)(sm+OAR+49152);            // 5120
        uint32_t* A1=(uint32_t*)(sm+OAR+54272);
        uint32_t a0=smem_u32(A0),a1=smem_u32(A1);
        float acc[1][4][2][4]={};
        path000(X1, X2, P.wpo[0], T2, X1S, acc);
        do_path<128,1,3,3, 64, 64,2>(X1+128,X2+128,P.wpo[4],scg+P.cgo[4],sx2h,A0,A1,a0,a1,acc);
        do_path<128,1,5,5, 32, 32,2>(X1+320,X2+320,P.wpo[9],scg+P.cgo[9],sx2h,A0,A1,a0,a1,acc);
        epilogue<128,1,0,2>(acc,out,tile,P.coeff[0]);
    } else if(blockIdx.x==1){
        uint32_t* A0=(uint32_t*)(sm+OAR);                  // 15360
        uint32_t* A1=(uint32_t*)(sm+OAR+15360);
        uint32_t a0=smem_u32(A0),a1=smem_u32(A1);
        float acc[3][4][1][4]={};
        do_path<64,3,1,3,128, 64,4>(X1,    X2+128,P.wpo[1],scg+P.cgo[1],sx2h,A0,A1,a0,a1,acc);
        do_path<64,3,3,1, 64,128,4>(X1+128,X2,    P.wpo[3],scg+P.cgo[3],sx2h,A0,A1,a0,a1,acc);
        do_path<64,3,3,5, 64, 32,4>(X1+128,X2+320,P.wpo[6],scg+P.cgo[6],sx2h,A0,A1,a0,a1,acc);
        do_path<64,3,5,3, 32, 64,4>(X1+320,X2+128,P.wpo[8],scg+P.cgo[8],sx2h,A0,A1,a0,a1,acc);
        epilogue<64,3,128,4>(acc,out,tile,P.coeff[1]);
    } else {
        uint32_t* A0=(uint32_t*)(sm+OAR);                  // 25600
        uint32_t* A1=(uint32_t*)(sm+OAR+25600);
        uint32_t a0=smem_u32(A0),a1=smem_u32(A1);
        float acc[5][2][1][4]={};
        do_path<32,5,1,5,128, 32,4>(X1,    X2+320,P.wpo[2], scg+P.cgo[2], sx2h,A0,A1,a0,a1,acc);
        do_path<32,5,3,3, 64, 64,4>(X1+128,X2+128,P.wpo[5], scg+P.cgo[5], sx2h,A0,A1,a0,a1,acc);
        do_path<32,5,5,1, 32,128,4>(X1+320,X2,    P.wpo[7], scg+P.cgo[7], sx2h,A0,A1,a0,a1,acc);
        do_path<32,5,5,5, 32, 32,4>(X1+320,X2+320,P.wpo[10],scg+P.cgo[10],sx2h,A0,A1,a0,a1,acc);
        epilogue<32,5,320,4>(acc,out,tile,P.coeff[2]);
    }
}

// ---------------------- host: CG construction (verified) --------------------

typedef std::complex<double> cpx;
static double fct(int n){double r=1.0;for(int i=2;i<=n;++i)r*=i;return r;}

static void change_basis(int l, cpx q[5][5]){
    for(int a=0;a<5;++a)for(int b=0;b<5;++b)q[a][b]=cpx(0,0);
    const double s2=1.0/std::sqrt(2.0);
    for(int m=-l;m<0;++m){ q[l+m][l-m]=cpx(s2,0); q[l+m][l+m]=cpx(0,-s2); }
    q[l][l]=cpx(1,0);
    for(int m=1;m<=l;++m){
        double sg=(m&1)?-1.0:1.0;
        q[l+m][l+m]=cpx(sg*s2,0); q[l+m][l-m]=cpx(0,sg*s2);
    }
    cpx ph(1,0);
    for(int t=0;t<l;++t)ph*=cpx(0,-1);
    for(int a=0;a<2*l+1;++a)for(int b=0;b<2*l+1;++b)q[a][b]*=ph;
}

static void real_cg(int l1,int l2,int l3,float outc[5][5][5]){
    cpx Q1[5][5],Q2[5][5],Q3[5][5];
    change_basis(l1,Q1); change_basis(l2,Q2); change_basis(l3,Q3);
    double C[5][5][5]; memset(C,0,sizeof(C));
    for(int m1=-l1;m1<=l1;++m1)
        for(int m2=-l2;m2<=l2;++m2){
            int m3=m1+m2;
            if(m3<-l3||m3>l3)continue;
            double pref=std::sqrt((2.0*l3+1.0)
                *fct(l3+l1-l2)*fct(l3-l1+l2)*fct(l1+l2-l3)/fct(l1+l2+l3+1)
                *fct(l3+m3)*fct(l3-m3)*fct(l1-m1)*fct(l1+m1)*fct(l2-m2)*fct(l2+m2));
            double s=0.0;
            for(int k=0;k<=l1+l2-l3;++k){
                if(l1-m1-k<0||l2+m2-k<0||l3-l2+m1+k<0||l3-l1-m2+k<0)continue;
                double d=fct(k)*fct(l1+l2-l3-k)*fct(l1-m1-k)
                        *fct(l2+m2-k)*fct(l3-l2+m1+k)*fct(l3-l1-m2+k);
                s+=((k&1)?-1.0:1.0)/d;
            }
            C[l1+m1][l2+m2][l3+m3]=pref*s;
        }
    int n1=2*l1+1,n2=2*l2+1,n3=2*l3+1;
    double Rr[5][5][5],nrm=0.0;
    for(int j=0;j<n1;++j)
        for(int lb=0;lb<n2;++lb)
            for(int nn=0;nn<n3;++nn){
                cpx a(0,0);
                for(int i=0;i<n1;++i)
                    for(int kk=0;kk<n2;++kk)
                        for(int m=0;m<n3;++m)
                            if(C[i][kk][m]!=0.0)
                                a+=Q1[i][j]*Q2[kk][lb]*Q3[m][nn]*C[i][kk][m];
                Rr[j][lb][nn]=a.real();
                nrm+=a.real()*a.real();
            }
    nrm=std::sqrt(nrm);
    for(int j=0;j<5;++j)for(int lb=0;lb<5;++lb)for(int nn=0;nn<5;++nn)
        outc[j][lb][nn]=(j<n1&&lb<n2&&nn<n3)?(float)(Rr[j][lb][nn]/nrm):0.f;
}

static void build_params(TPParams& P){
    memset(&P,0,sizeof(P));
    const int M_[3]={128,64,32}, L_[3]={0,1,2}, Pa[3]={1,-1,1};
    long long fan[3]={0,0,0};
    int woff=0, cgo=0, idx=0;
    for(int i1=0;i1<3;++i1)for(int i2=0;i2<3;++i2)for(int i3=0;i3<3;++i3){
        int l1=L_[i1],l2=L_[i2],l3=L_[i3];
        if(Pa[i1]*Pa[i2]!=Pa[i3])continue;
        if(l3<abs(l1-l2)||l3>l1+l2)continue;
        float C[5][5][5];
        real_cg(l1,l2,l3,C);
        P.woff[idx]=woff; P.cgo[idx]=cgo;
        P.wpo[idx]=woff/2; P.m3s[idx]=M_[i3];
        int n1=2*l1+1,n2=2*l2+1,n3=2*l3+1;
        for(int i=0;i<n1;++i)for(int j=0;j<n2;++j)for(int k=0;k<n3;++k)
            P.cg[cgo++]=C[i][j][k];
        woff+=M_[i1]*M_[i2]*M_[i3];
        fan[i3]+=(long long)M_[i1]*M_[i2];
        ++idx;
    }
    P.wpo[11]=woff/2;
    for(int t=0;t<3;++t)
        P.coeff[t]=(float)std::sqrt((double)(2*L_[t]+1)/(double)fan[t]);
}

// ------------------------------ entry ---------------------------------------

extern "C" void kernel_launch(void* const* d_in, const int* in_sizes, int n_in,
                              void* d_out, int out_size) {
    TPParams P;
    build_params(P);
    wpre_kernel<<<(P.wpo[11]+255)/256, 256>>>((const float*)d_in[2], P);
    cudaFuncSetAttribute(tp_kernel, cudaFuncAttributeMaxDynamicSharedMemorySize, SMT);
    tp_kernel<<<dim3(3,128), NT, SMT>>>(
        (const float*)d_in[0], (const float*)d_in[1], (float*)d_out, P);
}

// round 16
// speedup vs baseline: 2.4743x; 1.2515x over previous
#include <cuda_runtime.h>
#include <cuda_fp16.h>
#include <cstdint>
#include <cmath>
#include <cstring>
#include <complex>
#include <cstdlib>

#define NT 256
struct TPParams {
    float cg[384]; float coeff[3];
    int cgo[12], woff[12], wpo[12], m3s[12];
};

__device__ uint32_t g_wp[2244608];   // W half2, [path][chunk'][w][perm(kpair)]

#define OX2 1536
#define OAR 26880
#define SMT 92416

__device__ __host__ constexpr bool cg_nz(int L1,int L2,int L3,int i,int j,int k){
    int l1=(L1-1)/2, l2=(L2-1)/2, l3=(L3-1)/2;
    int a=i-l1; a=a<0?-a:a;
    int b=j-l2; b=b<0?-b:b;
    int c=k-l3; c=c<0?-c:c;
    int d=a-b; d=d<0?-d:d;
    return (c==a+b)||(c==d);
}

__device__ __forceinline__ uint32_t pack2(float lo, float hi){
    uint32_t r; asm("cvt.rn.f16x2.f32 %0,%1,%2;":"=r"(r):"f"(hi),"f"(lo)); return r;
}
__device__ __forceinline__ uint32_t hmul2u(uint32_t a, uint32_t b){
    uint32_t r; asm("mul.rn.f16x2 %0,%1,%2;":"=r"(r):"r"(a),"r"(b)); return r;
}
__device__ __forceinline__ uint32_t smem_u32(const void* p){
    uint32_t a;
    asm("{ .reg .u64 t; cvta.to.shared.u64 t, %1; cvt.u32.u64 %0, t; }":"=r"(a):"l"(p));
    return a;
}
__device__ __forceinline__ void mma16(float* d,const uint32_t* a,const uint32_t* b){
    asm volatile("mma.sync.aligned.m16n8k16.row.col.f32.f16.f16.f32 "
        "{%0,%1,%2,%3},{%4,%5,%6,%7},{%8,%9},{%0,%1,%2,%3};"
        :"+f"(d[0]),"+f"(d[1]),"+f"(d[2]),"+f"(d[3])
        :"r"(a[0]),"r"(a[1]),"r"(a[2]),"r"(a[3]),"r"(b[0]),"r"(b[1]));
}
#define LDSM4(r,addr) asm volatile( \
    "ldmatrix.sync.aligned.m8n8.x4.shared.b16 {%0,%1,%2,%3},[%4];" \
    :"=r"((r)[0]),"=r"((r)[1]),"=r"((r)[2]),"=r"((r)[3]):"r"(addr))

__global__ void wpre_kernel(const float* __restrict__ w,
                            const __grid_constant__ TPParams P){
    int r = blockIdx.x*256 + threadIdx.x;
    if(r >= P.wpo[11]) return;
    int t = 0;
    while(r >= P.wpo[t+1]) ++t;
    int loc = r - P.wpo[t], M3 = P.m3s[t];
    int n = loc/(16*M3), rem = loc - n*16*M3, w_ = rem>>4, pos = rem&15;
    int p = ((pos&3)<<2) + (pos>>2);
    int nl = (t==0) ? ((n&127)*4 + (n>>7)) : n;
    const float* s = w + P.woff[t] + (size_t)(nl*32 + 2*p)*M3 + w_;
    g_wp[r] = pack2(s[0], s[M3]);
}

// ---- path (0,0->0): barrier-free, A in regs --------------------------------
__device__ __forceinline__ void path000(
    const float* __restrict__ gx1, const float* __restrict__ gx2, int wpo,
    uint32_t* sx2t, uint32_t* x1s,
    float (&acc)[1][4][2][4])
{
    const int tid=threadIdx.x, wid=tid>>5, lane=tid&31;
    const int cgp=wid>>1, rowg=wid&1, gID=lane>>2, tIG=lane&3;
    __syncthreads();
    for(int idx=tid; idx<4096; idx+=NT){
        int cgr=idx>>10, rem=idx&1023, b=rem>>4, pos=rem&15;
        int p=((pos&3)<<2)+(pos>>2), v=cgr*32+2*p;
        sx2t[idx]=pack2(gx2[b*480+v], gx2[b*480+v+1]);
    }
    for(int idx=tid; idx<8192; idx+=NT){
        int u=idx>>6, row=idx&63;
        float v=gx1[row*480+u];
        x1s[idx]=pack2(v,v);
    }
    __syncthreads();
    const uint4* gB=(const uint4*)(g_wp+wpo)+(cgp*32+gID)*4+tIG;
    uint4 bv[4];
    auto ldB=[&](int n){
        const uint4* g=gB+(size_t)n*512;
        bv[0]=g[0]; bv[1]=g[32]; bv[2]=g[64]; bv[3]=g[96];
    };
    ldB(0);
#pragma unroll 1
    for(int cgr=0;cgr<4;++cgr){
        uint4 xv0[2], xv1[2];
#pragma unroll
        for(int r2=0;r2<2;++r2){
            const uint32_t* base=sx2t+cgr*1024+(rowg*32+r2*16+gID)*16+tIG*4;
            xv0[r2]=*(const uint4*)base;
            xv1[r2]=*(const uint4*)(base+128);
        }
#pragma unroll 1
        for(int u=0;u<128;++u){
            const int n=cgr*128+u;
            uint4 cur[4];
#pragma unroll
            for(int nc=0;nc<4;++nc) cur[nc]=bv[nc];
            if(n+1<512) ldB(n+1);
            uint32_t x1h[2][2];
#pragma unroll
            for(int r2=0;r2<2;++r2)
#pragma unroll
                for(int h=0;h<2;++h)
                    x1h[r2][h]=x1s[u*64+rowg*32+r2*16+gID+h*8];
#pragma unroll
            for(int ks=0;ks<2;++ks){
                uint32_t a[2][4];
#pragma unroll
                for(int r2=0;r2<2;++r2){
                    uint32_t s0=ks?xv0[r2].z:xv0[r2].x, s1=ks?xv1[r2].z:xv1[r2].x;
                    uint32_t s2=ks?xv0[r2].w:xv0[r2].y, s3=ks?xv1[r2].w:xv1[r2].y;
                    a[r2][0]=hmul2u(s0,x1h[r2][0]); a[r2][1]=hmul2u(s1,x1h[r2][1]);
                    a[r2][2]=hmul2u(s2,x1h[r2][0]); a[r2][3]=hmul2u(s3,x1h[r2][1]);
                }
#pragma unroll
                for(int nc=0;nc<4;++nc){
                    uint32_t bb[2];
                    bb[0]=ks?cur[nc].z:cur[nc].x;
                    bb[1]=ks?cur[nc].w:cur[nc].y;
#pragma unroll
                    for(int r2=0;r2<2;++r2)
                        mma16(acc[0][nc][r2],a[r2],bb);
                }
            }
        }
    }
}

// ---- pathY: l1==0. P = x1[b,u]*y_k[b,v]; y staged once; barrier-free -------
template<int M3,int L3,int L2,int M1,int M2>
__device__ __forceinline__ void pathY(
    const float* __restrict__ gx1, const float* __restrict__ gx2,
    int wpo, const float* __restrict__ cg,
    uint32_t* sy, uint32_t* x1s,
    float (&acc)[L3][M3/16][1][4])
{
    constexpr int CPW=M3/2, NC=M3/16, NCH=M1*M2/32;
    constexpr int BST=M2/2+4, KST=64*BST, VH=M2/32;
    const int tid=threadIdx.x, wid=tid>>5, lane=tid&31;
    const int cgp=wid>>2, rowg=wid&3, gID=lane>>2, tIG=lane&3;
    const int rbase=rowg*16+(lane&7)+((lane>>3)&1)*8;
    const int qb=((lane>>4)&1)*16;
    __syncthreads();
    for(int idx=tid; idx<64*(M2/2); idx+=NT){
        int b=idx/(M2/2), vp=idx-b*(M2/2);
        float xa[L2], xb[L2];
#pragma unroll
        for(int j=0;j<L2;++j){
            xa[j]=gx2[b*480+(2*vp)*L2+j];
            xb[j]=gx2[b*480+(2*vp+1)*L2+j];
        }
#pragma unroll
        for(int k=0;k<L3;++k){
            float ya=0.f, yb=0.f;
#pragma unroll
            for(int j=0;j<L2;++j)
                if(cg_nz(1,L2,L3,0,j,k)){
                    float cc=cg[j*L3+k];
                    ya+=cc*xa[j]; yb+=cc*xb[j];
                }
            sy[k*KST+b*BST+vp]=pack2(ya,yb);
        }
    }
    for(int idx=tid; idx<M1*64; idx+=NT){
        int u=idx>>6, row=idx&63;
        float v=gx1[row*480+u];
        x1s[idx]=pack2(v,v);
    }
    __syncthreads();
    const uint32_t sya=smem_u32(sy);
    const uint4* gB=(const uint4*)(g_wp+wpo)+(cgp*CPW+gID)*4+tIG;
    uint4 bv[NC];
    auto ldB=[&](int n){
        const uint4* g=gB+(size_t)n*(4*M3);
#pragma unroll
        for(int nc=0;nc<NC;++nc) bv[nc]=g[nc*32];
    };
    ldB(0);
#pragma unroll 1
    for(int n=0;n<NCH;++n){
        uint4 cur[NC];
#pragma unroll
        for(int nc=0;nc<NC;++nc) cur[nc]=bv[nc];
        if(n+1<NCH) ldB(n+1);
        const int u=n/VH, vh=n%VH;
        uint32_t x1h[2];
        x1h[0]=x1s[u*64+rowg*16+gID];
        x1h[1]=x1s[u*64+rowg*16+gID+8];
#pragma unroll
        for(int ks=0;ks<2;++ks){
            uint32_t bb[NC][2];
#pragma unroll
            for(int nc=0;nc<NC;++nc){
                bb[nc][0]=ks?cur[nc].z:cur[nc].x;
                bb[nc][1]=ks?cur[nc].w:cur[nc].y;
            }
#pragma unroll
            for(int k=0;k<L3;++k){
                uint32_t yf[4], a[4];
                LDSM4(yf, sya+(k*KST+rbase*BST)*4+qb+ks*32+vh*64);
                a[0]=hmul2u(yf[0],x1h[0]); a[1]=hmul2u(yf[1],x1h[1]);
                a[2]=hmul2u(yf[2],x1h[0]); a[3]=hmul2u(yf[3],x1h[1]);
#pragma unroll
                for(int nc=0;nc<NC;++nc)
                    mma16(acc[k][nc][0],a,bb[nc]);
            }
        }
    }
}

// ---- pathZ: l2==0 (M2=128). P = z_k[b,u]*x2[b,v]; barrier-free -------------
template<int M3,int L3,int L1,int M1>
__device__ __forceinline__ void pathZ(
    const float* __restrict__ gx1, const float* __restrict__ gx2,
    int wpo, const float* __restrict__ cg,
    uint32_t* sx2t, uint32_t* zs,
    float (&acc)[L3][M3/16][1][4])
{
    constexpr int CPW=M3/2, NC=M3/16, NCH=M1*4;
    const int tid=threadIdx.x, wid=tid>>5, lane=tid&31;
    const int cgp=wid>>2, rowg=wid&3, gID=lane>>2, tIG=lane&3;
    __syncthreads();
    for(int idx=tid; idx<4096; idx+=NT){
        int cgr=idx>>10, rem=idx&1023, b=rem>>4, pos=rem&15;
        int p=((pos&3)<<2)+(pos>>2), v=cgr*32+2*p;
        sx2t[idx]=pack2(gx2[b*480+v], gx2[b*480+v+1]);
    }
    for(int idx=tid; idx<M1*64; idx+=NT){
        int u=idx>>6, row=idx&63;
        float xi[L1];
#pragma unroll
        for(int i=0;i<L1;++i) xi[i]=gx1[row*480+u*L1+i];
#pragma unroll
        for(int k=0;k<L3;++k){
            float z=0.f;
#pragma unroll
            for(int i=0;i<L1;++i)
                if(cg_nz(L1,1,L3,i,0,k)) z+=cg[i*L3+k]*xi[i];
            zs[(k*M1+u)*64+row]=pack2(z,z);
        }
    }
    __syncthreads();
    const uint4* gB=(const uint4*)(g_wp+wpo)+(cgp*CPW+gID)*4+tIG;
    uint4 bv[NC];
    auto ldB=[&](int n){
        const uint4* g=gB+(size_t)n*(4*M3);
#pragma unroll
        for(int nc=0;nc<NC;++nc) bv[nc]=g[nc*32];
    };
    ldB(0);
#pragma unroll 1
    for(int n=0;n<NCH;++n){
        uint4 cur[NC];
#pragma unroll
        for(int nc=0;nc<NC;++nc) cur[nc]=bv[nc];
        if(n+1<NCH) ldB(n+1);
        const int u=n>>2, vg=n&3;
        const uint32_t* base=sx2t+vg*1024+(rowg*16+gID)*16+tIG*4;
        uint4 xv0=*(const uint4*)base;
        uint4 xv1=*(const uint4*)(base+128);
        uint32_t zh[L3][2];
#pragma unroll
        for(int k=0;k<L3;++k){
            zh[k][0]=zs[(k*M1+u)*64+rowg*16+gID];
            zh[k][1]=zs[(k*M1+u)*64+rowg*16+gID+8];
        }
#pragma unroll
        for(int ks=0;ks<2;++ks){
            uint32_t s0=ks?xv0.z:xv0.x, s1=ks?xv1.z:xv1.x;
            uint32_t s2=ks?xv0.w:xv0.y, s3=ks?xv1.w:xv1.y;
            uint32_t bb[NC][2];
#pragma unroll
            for(int nc=0;nc<NC;++nc){
                bb[nc][0]=ks?cur[nc].z:cur[nc].x;
                bb[nc][1]=ks?cur[nc].w:cur[nc].y;
            }
#pragma unroll
            for(int k=0;k<L3;++k){
                uint32_t a[4];
                a[0]=hmul2u(s0,zh[k][0]); a[1]=hmul2u(s1,zh[k][1]);
                a[2]=hmul2u(s2,zh[k][0]); a[3]=hmul2u(s3,zh[k][1]);
#pragma unroll
                for(int nc=0;nc<NC;++nc)
                    mma16(acc[k][nc][0],a,bb[nc]);
            }
        }
    }
}

// ---- generic fused path (remaining small paths) ----------------------------
template<int M3,int L3,int L1,int L2,int M1,int M2,int RG>
__device__ __forceinline__ void do_path(
    const float* __restrict__ gx1, const float* __restrict__ gx2,
    int wpo, const float* __restrict__ cg,
    uint32_t* sx2h, uint32_t* sA0, uint32_t* sA1, uint32_t sA0a, uint32_t sA1a,
    float (&acc)[L3][M3*RG/64][4/RG][4])
{
    constexpr int CGn=8/RG, CPW=M3/CGn, NC=CPW/8, R2=4/RG;
    constexpr int NCH=M1*M2/32, C=(M2/2)*L2;
    const int tid=threadIdx.x, wid=tid>>5, lane=tid&31;
    const int cgp=wid/RG, rowg=wid%RG, gID=lane>>2, tIG=lane&3;
    const int q=tid&15, bg=tid>>4;
    const int rbase=rowg*(64/RG)+(lane&7)+((lane>>3)&1)*8;
    const int qb=((lane>>4)&1)*16;

    __syncthreads();
    for(int idx=tid; idx<64*C; idx+=NT){
        int b=idx/C, c=idx-b*C, vp=c/L2, j=c-vp*L2;
        float lo=gx2[b*480+(2*vp)*L2+j], hi=gx2[b*480+(2*vp+1)*L2+j];
        sx2h[c*66+b]=pack2(lo,hi);
    }
    __syncthreads();

    float rx1[4][L1];
    auto loadx1=[&](int u){
#pragma unroll
        for(int it=0;it<4;++it)
#pragma unroll
            for(int i=0;i<L1;++i)
                rx1[it][i]=gx1[(it*16+bg)*480+u*L1+i];
    };
    const uint4* gB=(const uint4*)(g_wp+wpo)+(cgp*CPW+gID)*4+tIG;
    uint4 bv[NC];
    auto ldB=[&](int n){
        const uint4* g=gB+(size_t)n*(4*M3);
#pragma unroll
        for(int nc=0;nc<NC;++nc) bv[nc]=g[nc*32];
    };
    auto compP=[&](int n){
        uint32_t* d=(n&1)?sA1:sA0;
        const int vp0=((n*32)&(M2-1))>>1;
        const uint32_t* c2=sx2h+(vp0+q)*L2*66;
#pragma unroll
        for(int it=0;it<4;++it){
            const int b=it*16+bg;
            float2 cf[L2];
#pragma unroll
            for(int j=0;j<L2;++j){
                uint32_t cw=c2[j*66+b];
                cf[j]=__half22float2(*(__half2*)&cw);
            }
            float pa[L3], pb[L3];
#pragma unroll
            for(int k=0;k<L3;++k){ pa[k]=0.f; pb[k]=0.f; }
#pragma unroll
            for(int i=0;i<L1;++i){
                const float xi=rx1[it][i];
#pragma unroll
                for(int j=0;j<L2;++j){
                    float xa=xi*cf[j].x, xb=xi*cf[j].y;
#pragma unroll
                    for(int k=0;k<L3;++k){
                        if(cg_nz(L1,L2,L3,i,j,k)){
                            float cc=cg[(i*L2+j)*L3+k];
                            pa[k]+=cc*xa; pb[k]+=cc*xb;
                        }
                    }
                }
            }
#pragma unroll
            for(int k=0;k<L3;++k) d[k*1280+b*20+q]=pack2(pa[k],pb[k]);
        }
    };

    loadx1(0); compP(0); ldB(0);
#pragma unroll 1
    for(int n=0;n<NCH;++n){
        __syncthreads();
        const uint32_t sAa=(n&1)?sA1a:sA0a;
        uint32_t breg[2][NC][2];
#pragma unroll
        for(int nc=0;nc<NC;++nc){
            breg[0][nc][0]=bv[nc].x; breg[0][nc][1]=bv[nc].y;
            breg[1][nc][0]=bv[nc].z; breg[1][nc][1]=bv[nc].w;
        }
#pragma unroll
        for(int ks=0;ks<2;++ks){
            uint32_t a[L3][R2][4];
#pragma unroll
            for(int k=0;k<L3;++k)
#pragma unroll
                for(int r2=0;r2<R2;++r2)
                    LDSM4(a[k][r2], sAa+(k*1280+(rbase+r2*16)*20)*4+qb+ks*32);
#pragma unroll
            for(int k=0;k<L3;++k)
#pragma unroll
                for(int nc=0;nc<NC;++nc)
#pragma unroll
                    for(int r2=0;r2<R2;++r2)
                        mma16(acc[k][nc][r2],a[k][r2],breg[ks][nc]);
        }
        if(n+1<NCH){
            ldB(n+1);
            if((((n+1)*32)&(M2-1))==0) loadx1((n+1)*32/M2);
            compP(n+1);
        }
    }
}

template<int M3,int L3,int OFF3,int RG>
__device__ __forceinline__ void epilogue(float (&acc)[L3][M3*RG/64][4/RG][4],
    float* __restrict__ out,int tile,float coeff)
{
    constexpr int CGn=8/RG, CPW=M3/CGn, NC=CPW/8, R2=4/RG;
    const int tid=threadIdx.x, wid=tid>>5, lane=tid&31;
    const int cgp=wid/RG, rowg=wid%RG, gID=lane>>2, tIG=lane&3;
#pragma unroll
    for(int k=0;k<L3;++k)
#pragma unroll
        for(int nc=0;nc<NC;++nc)
#pragma unroll
            for(int r2=0;r2<R2;++r2){
                const int wc=cgp*CPW+nc*8+2*tIG;
                const int row=tile*64+rowg*(64/RG)+r2*16+gID;
                float* po=out+(size_t)row*480+OFF3;
                po[(wc+0)*L3+k]=coeff*acc[k][nc][r2][0];
                po[(wc+1)*L3+k]=coeff*acc[k][nc][r2][1];
                po+=8*480;
                po[(wc+0)*L3+k]=coeff*acc[k][nc][r2][2];
                po[(wc+1)*L3+k]=coeff*acc[k][nc][r2][3];
            }
}

__global__ void __launch_bounds__(NT,2)
tp_kernel(const float* __restrict__ x1,const float* __restrict__ x2,
          float* __restrict__ out,const __grid_constant__ TPParams P)
{
    extern __shared__ char sm[];
    float* scg=(float*)sm;
    for(int e=threadIdx.x;e<384;e+=NT) scg[e]=P.cg[e];
    const int tile=blockIdx.y;
    const float* X1=x1+(size_t)tile*64*480;
    const float* X2=x2+(size_t)tile*64*480;
    uint32_t* sx2h=(uint32_t*)(sm+OX2);

    if(blockIdx.x==0){
        uint32_t* T2=(uint32_t*)(sm+OAR);
        uint32_t* X1S=(uint32_t*)(sm+OAR+16384);
        uint32_t* A0=(uint32_t*)(sm+OAR+49152);
        uint32_t* A1=(uint32_t*)(sm+OAR+54272);
        uint32_t a0=smem_u32(A0),a1=smem_u32(A1);
        float acc[1][4][2][4]={};
        path000(X1, X2, P.wpo[0], T2, X1S, acc);
        do_path<128,1,3,3, 64, 64,2>(X1+128,X2+128,P.wpo[4],scg+P.cgo[4],sx2h,A0,A1,a0,a1,acc);
        do_path<128,1,5,5, 32, 32,2>(X1+320,X2+320,P.wpo[9],scg+P.cgo[9],sx2h,A0,A1,a0,a1,acc);
        epilogue<128,1,0,2>(acc,out,tile,P.coeff[0]);
    } else if(blockIdx.x==1){
        uint32_t* SY=(uint32_t*)(sm+OAR);                  // 27648
        uint32_t* X1S=(uint32_t*)(sm+OAR+27648);           // 32768
        uint32_t* SX2T=(uint32_t*)(sm+OAR);                // 16384
        uint32_t* ZS=(uint32_t*)(sm+OAR+16384);            // 49152
        uint32_t* A0=(uint32_t*)(sm+OAR);
        uint32_t* A1=(uint32_t*)(sm+OAR+15360);
        uint32_t a0=smem_u32(A0),a1=smem_u32(A1);
        float acc[3][4][1][4]={};
        pathY<64,3,3,128,64>(X1,    X2+128,P.wpo[1],scg+P.cgo[1],SY,X1S,acc);
        pathZ<64,3,3, 64>   (X1+128,X2,    P.wpo[3],scg+P.cgo[3],SX2T,ZS,acc);
        do_path<64,3,3,5, 64, 32,4>(X1+128,X2+320,P.wpo[6],scg+P.cgo[6],sx2h,A0,A1,a0,a1,acc);
        do_path<64,3,5,3, 32, 64,4>(X1+320,X2+128,P.wpo[8],scg+P.cgo[8],sx2h,A0,A1,a0,a1,acc);
        epilogue<64,3,128,4>(acc,out,tile,P.coeff[1]);
    } else {
        uint32_t* SY=(uint32_t*)(sm+OAR);                  // 25600
        uint32_t* X1S=(uint32_t*)(sm+OAR+25600);           // 32768
        uint32_t* SX2T=(uint32_t*)(sm+OAR);                // 16384
        uint32_t* ZS=(uint32_t*)(sm+OAR+16384);            // 40960
        uint32_t* A0=(uint32_t*)(sm+OAR);
        uint32_t* A1=(uint32_t*)(sm+OAR+25600);
        uint32_t a0=smem_u32(A0),a1=smem_u32(A1);
        float acc[5][2][1][4]={};
        pathY<32,5,5,128,32>(X1,    X2+320,P.wpo[2], scg+P.cgo[2], SY,X1S,acc);
        do_path<32,5,3,3, 64, 64,4>(X1+128,X2+128,P.wpo[5], scg+P.cgo[5], sx2h,A0,A1,a0,a1,acc);
        pathZ<32,5,5, 32>   (X1+320,X2,    P.wpo[7], scg+P.cgo[7], SX2T,ZS,acc);
        do_path<32,5,5,5, 32, 32,4>(X1+320,X2+320,P.wpo[10],scg+P.cgo[10],sx2h,A0,A1,a0,a1,acc);
        epilogue<32,5,320,4>(acc,out,tile,P.coeff[2]);
    }
}

// ---------------------- host: CG construction (verified) --------------------

typedef std::complex<double> cpx;
static double fct(int n){double r=1.0;for(int i=2;i<=n;++i)r*=i;return r;}

static void change_basis(int l, cpx q[5][5]){
    for(int a=0;a<5;++a)for(int b=0;b<5;++b)q[a][b]=cpx(0,0);
    const double s2=1.0/std::sqrt(2.0);
    for(int m=-l;m<0;++m){ q[l+m][l-m]=cpx(s2,0); q[l+m][l+m]=cpx(0,-s2); }
    q[l][l]=cpx(1,0);
    for(int m=1;m<=l;++m){
        double sg=(m&1)?-1.0:1.0;
        q[l+m][l+m]=cpx(sg*s2,0); q[l+m][l-m]=cpx(0,sg*s2);
    }
    cpx ph(1,0);
    for(int t=0;t<l;++t)ph*=cpx(0,-1);
    for(int a=0;a<2*l+1;++a)for(int b=0;b<2*l+1;++b)q[a][b]*=ph;
}

static void real_cg(int l1,int l2,int l3,float outc[5][5][5]){
    cpx Q1[5][5],Q2[5][5],Q3[5][5];
    change_basis(l1,Q1); change_basis(l2,Q2); change_basis(l3,Q3);
    double C[5][5][5]; memset(C,0,sizeof(C));
    for(int m1=-l1;m1<=l1;++m1)
        for(int m2=-l2;m2<=l2;++m2){
            int m3=m1+m2;
            if(m3<-l3||m3>l3)continue;
            double pref=std::sqrt((2.0*l3+1.0)
                *fct(l3+l1-l2)*fct(l3-l1+l2)*fct(l1+l2-l3)/fct(l1+l2+l3+1)
                *fct(l3+m3)*fct(l3-m3)*fct(l1-m1)*fct(l1+m1)*fct(l2-m2)*fct(l2+m2));
            double s=0.0;
            for(int k=0;k<=l1+l2-l3;++k){
                if(l1-m1-k<0||l2+m2-k<0||l3-l2+m1+k<0||l3-l1-m2+k<0)continue;
                double d=fct(k)*fct(l1+l2-l3-k)*fct(l1-m1-k)
                        *fct(l2+m2-k)*fct(l3-l2+m1+k)*fct(l3-l1-m2+k);
                s+=((k&1)?-1.0:1.0)/d;
            }
            C[l1+m1][l2+m2][l3+m3]=pref*s;
        }
    int n1=2*l1+1,n2=2*l2+1,n3=2*l3+1;
    double Rr[5][5][5],nrm=0.0;
    for(int j=0;j<n1;++j)
        for(int lb=0;lb<n2;++lb)
            for(int nn=0;nn<n3;++nn){
                cpx a(0,0);
                for(int i=0;i<n1;++i)
                    for(int kk=0;kk<n2;++kk)
                        for(int m=0;m<n3;++m)
                            if(C[i][kk][m]!=0.0)
                                a+=Q1[i][j]*Q2[kk][lb]*Q3[m][nn]*C[i][kk][m];
                Rr[j][lb][nn]=a.real();
                nrm+=a.real()*a.real();
            }
    nrm=std::sqrt(nrm);
    for(int j=0;j<5;++j)for(int lb=0;lb<5;++lb)for(int nn=0;nn<5;++nn)
        outc[j][lb][nn]=(j<n1&&lb<n2&&nn<n3)?(float)(Rr[j][lb][nn]/nrm):0.f;
}

static void build_params(TPParams& P){
    memset(&P,0,sizeof(P));
    const int M_[3]={128,64,32}, L_[3]={0,1,2}, Pa[3]={1,-1,1};
    long long fan[3]={0,0,0};
    int woff=0, cgo=0, idx=0;
    for(int i1=0;i1<3;++i1)for(int i2=0;i2<3;++i2)for(int i3=0;i3<3;++i3){
        int l1=L_[i1],l2=L_[i2],l3=L_[i3];
        if(Pa[i1]*Pa[i2]!=Pa[i3])continue;
        if(l3<abs(l1-l2)||l3>l1+l2)continue;
        float C[5][5][5];
        real_cg(l1,l2,l3,C);
        P.woff[idx]=woff; P.cgo[idx]=cgo;
        P.wpo[idx]=woff/2; P.m3s[idx]=M_[i3];
        int n1=2*l1+1,n2=2*l2+1,n3=2*l3+1;
        for(int i=0;i<n1;++i)for(int j=0;j<n2;++j)for(int k=0;k<n3;++k)
            P.cg[cgo++]=C[i][j][k];
        woff+=M_[i1]*M_[i2]*M_[i3];
        fan[i3]+=(long long)M_[i1]*M_[i2];
        ++idx;
    }
    P.wpo[11]=woff/2;
    for(int t=0;t<3;++t)
        P.coeff[t]=(float)std::sqrt((double)(2*L_[t]+1)/(double)fan[t]);
}

// ------------------------------ entry ---------------------------------------

extern "C" void kernel_launch(void* const* d_in, const int* in_sizes, int n_in,
                              void* d_out, int out_size) {
    TPParams P;
    build_params(P);
    wpre_kernel<<<(P.wpo[11]+255)/256, 256>>>((const float*)d_in[2], P);
    cudaFuncSetAttribute(tp_kernel, cudaFuncAttributeMaxDynamicSharedMemorySize, SMT);
    tp_kernel<<<dim3(3,128), NT, SMT>>>(
        (const float*)d_in[0], (const float*)d_in[1], (float*)d_out, P);
}